// round 1
// baseline (speedup 1.0000x reference)
#include <cuda_runtime.h>

#define D_MODEL 1024
#define NHEAD   16
#define DK      64
#define BB      2
#define SEQ     2048
#define MROWS   (BB * SEQ)   // 4096
#define NBH     (BB * NHEAD) // 32

// ---------------- scratch (device globals; allocation-free rule) ------------
__device__ float g_qh [NBH * SEQ * DK];   // [bh][s][d], pre-scaled by 1/8
__device__ float g_kT [NBH * DK * SEQ];   // [bh][d][s]  (transposed K)
__device__ float g_vh [NBH * SEQ * DK];   // [bh][s][d]
__device__ float g_ctx[MROWS * D_MODEL];  // [b*S + s][h*64 + d]

// ---------------- 128x128x8 fp32 tiled GEMM body ----------------------------
// C[M=4096,N=1024] = A[4096,1024] @ W[1024,1024] (+bias), epilogue by mode:
//   mode 0: out[m*1024+n]                         (plain row-major)
//   mode 1: qh layout, value *= 0.125f            (fold 1/sqrt(dk))
//   mode 2: kT layout [bh][d][s]
//   mode 3: vh layout [bh][s][d]
__device__ __forceinline__ void gemm128(
    const float* __restrict__ A, const float* __restrict__ W,
    const float* __restrict__ bias, float* __restrict__ out,
    int mode, float* As, float* Bs)
{
    const int t  = threadIdx.x;
    const int bm = blockIdx.y * 128;
    const int bn = blockIdx.x * 128;

    const int arow = t >> 1;            // 0..127
    const int acol = (t & 1) * 4;       // 0 or 4
    const int brow = t >> 5;            // 0..7
    const int bcol = (t & 31) * 4;      // 0..124
    const int tx = t & 15, ty = t >> 4; // 16 x 16 thread grid, 8x8 micro

    float acc[8][8];
#pragma unroll
    for (int i = 0; i < 8; ++i)
#pragma unroll
        for (int j = 0; j < 8; ++j) acc[i][j] = 0.f;

    const float* aptr = A + (size_t)(bm + arow) * 1024 + acol;
    const float* bptr = W + (size_t)brow * 1024 + bn + bcol;

    for (int k0 = 0; k0 < 1024; k0 += 8) {
        float4 av = *(const float4*)(aptr + k0);
        float4 bv = *(const float4*)(bptr + (size_t)k0 * 1024);
        __syncthreads();                       // protect prev iteration reads
        As[(acol + 0) * 128 + arow] = av.x;
        As[(acol + 1) * 128 + arow] = av.y;
        As[(acol + 2) * 128 + arow] = av.z;
        As[(acol + 3) * 128 + arow] = av.w;
        *(float4*)&Bs[brow * 128 + bcol] = bv;
        __syncthreads();
#pragma unroll
        for (int kk = 0; kk < 8; ++kk) {
            float ar[8], br[8];
            *(float4*)&ar[0] = *(float4*)&As[kk * 128 + ty * 8];
            *(float4*)&ar[4] = *(float4*)&As[kk * 128 + ty * 8 + 4];
            *(float4*)&br[0] = *(float4*)&Bs[kk * 128 + tx * 8];
            *(float4*)&br[4] = *(float4*)&Bs[kk * 128 + tx * 8 + 4];
#pragma unroll
            for (int i = 0; i < 8; ++i)
#pragma unroll
                for (int j = 0; j < 8; ++j)
                    acc[i][j] = fmaf(ar[i], br[j], acc[i][j]);
        }
    }

#pragma unroll
    for (int i = 0; i < 8; ++i) {
        const int m = bm + ty * 8 + i;
        const int b = m >> 11, s = m & 2047;
#pragma unroll
        for (int j = 0; j < 8; ++j) {
            const int n = bn + tx * 8 + j;
            float v = acc[i][j] + bias[n];
            if (mode == 0) {
                out[(size_t)m * 1024 + n] = v;
            } else {
                const int h = n >> 6, d = n & 63;
                const int bh = b * NHEAD + h;
                if (mode == 1)
                    out[((size_t)bh * SEQ + s) * DK + d] = v * 0.125f;
                else if (mode == 2)
                    out[((size_t)bh * DK + d) * SEQ + s] = v;
                else
                    out[((size_t)bh * SEQ + s) * DK + d] = v;
            }
        }
    }
}

__global__ void __launch_bounds__(256) qkv_gemm(
    const float* __restrict__ q, const float* __restrict__ k,
    const float* __restrict__ v,
    const float* __restrict__ wq, const float* __restrict__ bq,
    const float* __restrict__ wk, const float* __restrict__ bk,
    const float* __restrict__ wv, const float* __restrict__ bv)
{
    __shared__ float As[8 * 128];
    __shared__ float Bs[8 * 128];
    const int z = blockIdx.z;
    const float* A    = (z == 0) ? q  : (z == 1) ? k  : v;
    const float* W    = (z == 0) ? wq : (z == 1) ? wk : wv;
    const float* bias = (z == 0) ? bq : (z == 1) ? bk : bv;
    float* out        = (z == 0) ? g_qh : (z == 1) ? g_kT : g_vh;
    gemm128(A, W, bias, out, z + 1, As, Bs);
}

__global__ void __launch_bounds__(256) out_gemm(
    const float* __restrict__ wo, const float* __restrict__ bo,
    float* __restrict__ out)
{
    __shared__ float As[8 * 128];
    __shared__ float Bs[8 * 128];
    gemm128(g_ctx, wo, bo, out, 0, As, Bs);
}

// ---------------- attention: scores + softmax + attn write + P@V ------------
// grid (128, 32): blockIdx.y = bh, blockIdx.x = 16-query tile. 256 threads.
// smem: sc[16][2048] (128KB) | kvs[8192] (32KB, K-chunk transposed / V-chunk)
//       | qs[16][64] (4KB)  => 167936 B dynamic
__global__ void __launch_bounds__(256) attn_k(float* __restrict__ attn_out)
{
    extern __shared__ float sm[];
    float* sc  = sm;               // 16 * 2048
    float* kvs = sm + 16 * 2048;   // 64*128 (K^T chunk) or 128*64 (V chunk)
    float* qs  = kvs + 8192;       // 16 * 64

    const int t    = threadIdx.x;
    const int lane = t & 31;
    const int wid  = t >> 5;       // 0..7
    const int bh   = blockIdx.y;   // 0..31
    const int q0   = blockIdx.x * 16;

    // load Q tile (pre-scaled by 1/8 in projection)
    {
        const float* qbase = g_qh + ((size_t)bh * SEQ + q0) * DK;
        const int i = t >> 4, d4 = (t & 15) * 4;
        *(float4*)&qs[i * DK + d4] = *(const float4*)&qbase[i * DK + d4];
    }

    // ---- scores: S[16][2048] = Q K^T -------------------------------------
    const float* kT = g_kT + (size_t)bh * DK * SEQ;
    const int i0 = wid * 2;
    for (int c = 0; c < 16; ++c) {
        __syncthreads();                    // kvs reuse + first-iter q guard
#pragma unroll
        for (int r = 0; r < 8; ++r) {       // load K chunk: kvs[d][j], j=0..127
            const int lin = r * 256 + t;    // float4 units
            const int d  = lin >> 5;        // 0..63
            const int j4 = (lin & 31) * 4;
            *(float4*)&kvs[d * 128 + j4] =
                *(const float4*)&kT[(size_t)d * SEQ + c * 128 + j4];
        }
        __syncthreads();
        float4 r0 = {0, 0, 0, 0}, r1 = {0, 0, 0, 0};
#pragma unroll 8
        for (int d = 0; d < 64; ++d) {
            const float qa = qs[i0 * DK + d];
            const float qb = qs[(i0 + 1) * DK + d];
            const float4 kv = *(const float4*)&kvs[d * 128 + lane * 4];
            r0.x = fmaf(qa, kv.x, r0.x); r0.y = fmaf(qa, kv.y, r0.y);
            r0.z = fmaf(qa, kv.z, r0.z); r0.w = fmaf(qa, kv.w, r0.w);
            r1.x = fmaf(qb, kv.x, r1.x); r1.y = fmaf(qb, kv.y, r1.y);
            r1.z = fmaf(qb, kv.z, r1.z); r1.w = fmaf(qb, kv.w, r1.w);
        }
        *(float4*)&sc[i0 * SEQ + c * 128 + lane * 4]       = r0;
        *(float4*)&sc[(i0 + 1) * SEQ + c * 128 + lane * 4] = r1;
    }
    __syncthreads();

    // ---- softmax per row (warp wid owns rows 2wid, 2wid+1) ----------------
    float* attn_base = attn_out + ((size_t)bh * SEQ + q0) * SEQ;
#pragma unroll
    for (int rr = 0; rr < 2; ++rr) {
        const int i = i0 + rr;
        float* row = &sc[i * SEQ];
        float mx = -1e30f;
#pragma unroll
        for (int kx = 0; kx < 64; ++kx) mx = fmaxf(mx, row[lane + kx * 32]);
#pragma unroll
        for (int o = 16; o; o >>= 1) mx = fmaxf(mx, __shfl_xor_sync(~0u, mx, o));
        float sum = 0.f;
#pragma unroll
        for (int kx = 0; kx < 64; ++kx) {
            const float e = __expf(row[lane + kx * 32] - mx);
            row[lane + kx * 32] = e;
            sum += e;
        }
#pragma unroll
        for (int o = 16; o; o >>= 1) sum += __shfl_xor_sync(~0u, sum, o);
        const float inv = 1.0f / sum;
        float* grow = attn_base + (size_t)i * SEQ;
#pragma unroll
        for (int kx = 0; kx < 16; ++kx) {
            const int j4 = (lane + kx * 32) * 4;
            float4 p = *(float4*)&row[j4];
            p.x *= inv; p.y *= inv; p.z *= inv; p.w *= inv;
            *(float4*)&row[j4]  = p;
            *(float4*)&grow[j4] = p;
        }
    }

    // ---- ctx = P @ V -------------------------------------------------------
    const float* vb = g_vh + (size_t)bh * SEQ * DK;
    const int ci = t >> 4;          // 0..15 (query row; warp-coherent)
    const int cd = (t & 15) * 4;    // d base
    float4 acc = {0, 0, 0, 0};
    for (int c = 0; c < 16; ++c) {
        __syncthreads();            // kvs reuse (also orders softmax -> ctx)
#pragma unroll
        for (int r = 0; r < 8; ++r) { // load V chunk: kvs[kk][d], natural
            const int lin = r * 256 + t;
            const int kk = lin >> 4;          // 0..127
            const int d4 = (lin & 15) * 4;
            *(float4*)&kvs[kk * DK + d4] =
                *(const float4*)&vb[((size_t)c * 128 + kk) * DK + d4];
        }
        __syncthreads();
        const float* prow = &sc[ci * SEQ + c * 128];
#pragma unroll 2
        for (int kk = 0; kk < 128; kk += 4) {
            const float4 p  = *(const float4*)&prow[kk];
            const float4 v0 = *(const float4*)&kvs[(kk + 0) * DK + cd];
            const float4 v1 = *(const float4*)&kvs[(kk + 1) * DK + cd];
            const float4 v2 = *(const float4*)&kvs[(kk + 2) * DK + cd];
            const float4 v3 = *(const float4*)&kvs[(kk + 3) * DK + cd];
            acc.x = fmaf(p.x, v0.x, acc.x); acc.y = fmaf(p.x, v0.y, acc.y);
            acc.z = fmaf(p.x, v0.z, acc.z); acc.w = fmaf(p.x, v0.w, acc.w);
            acc.x = fmaf(p.y, v1.x, acc.x); acc.y = fmaf(p.y, v1.y, acc.y);
            acc.z = fmaf(p.y, v1.z, acc.z); acc.w = fmaf(p.y, v1.w, acc.w);
            acc.x = fmaf(p.z, v2.x, acc.x); acc.y = fmaf(p.z, v2.y, acc.y);
            acc.z = fmaf(p.z, v2.z, acc.z); acc.w = fmaf(p.z, v2.w, acc.w);
            acc.x = fmaf(p.w, v3.x, acc.x); acc.y = fmaf(p.w, v3.y, acc.y);
            acc.z = fmaf(p.w, v3.z, acc.z); acc.w = fmaf(p.w, v3.w, acc.w);
        }
    }
    // ctx layout [b*S+s][h*64+d]
    const int b = bh >> 4, h = bh & 15;
    *(float4*)&g_ctx[(((size_t)b * SEQ + q0 + ci) * NHEAD + h) * DK + cd] = acc;
}

// ---------------- launch -----------------------------------------------------
extern "C" void kernel_launch(void* const* d_in, const int* in_sizes, int n_in,
                              void* d_out, int out_size)
{
    (void)in_sizes; (void)n_in; (void)out_size;
    const float* q  = (const float*)d_in[0];
    const float* k  = (const float*)d_in[1];
    const float* v  = (const float*)d_in[2];
    const float* wq = (const float*)d_in[3];
    const float* bq = (const float*)d_in[4];
    const float* wk = (const float*)d_in[5];
    const float* bk = (const float*)d_in[6];
    const float* wv = (const float*)d_in[7];
    const float* bv = (const float*)d_in[8];
    const float* wo = (const float*)d_in[9];
    const float* bo = (const float*)d_in[10];

    float* out  = (float*)d_out;                       // [B,S,D]
    float* attn = out + (size_t)MROWS * D_MODEL;       // [B,H,S,S]

    const int smem = (16 * 2048 + 8192 + 16 * 64) * 4; // 167936
    cudaFuncSetAttribute(attn_k, cudaFuncAttributeMaxDynamicSharedMemorySize, smem);

    qkv_gemm<<<dim3(8, 32, 3), 256>>>(q, k, v, wq, bq, wk, bk, wv, bv);
    attn_k<<<dim3(128, 32), 256, smem>>>(attn);
    out_gemm<<<dim3(8, 32), 256>>>(wo, bo, out);
}

// round 2
// speedup vs baseline: 1.6673x; 1.6673x over previous
#include <cuda_runtime.h>
#include <cstdint>

#define D_MODEL 1024
#define NHEAD   16
#define DK      64
#define BB      2
#define SEQ     2048
#define MROWS   (BB * SEQ)   // 4096
#define NBH     (BB * NHEAD) // 32

// padded smem strides (floats) — chosen for conflict-free mma fragment LDS
#define SCP   2052           // score strip row stride (2048 + 4)
#define KSTR  136            // K chunk: [64 d][128 keys] stride (mod32 = 8)
#define VSTR  72             // V chunk: [128 keys][64 d] stride (mod32 = 8)
#define QSTR  68             // Q tile stride (mod32 = 4)
#define KVBUF 9216           // per double-buffer (max of 64*136, 128*72)

// ---------------- scratch (device globals; allocation-free rule) ------------
__device__ float g_qh [NBH * SEQ * DK];   // [bh][s][d], pre-scaled by 1/8
__device__ float g_kT [NBH * DK * SEQ];   // [bh][d][s]  (transposed K)
__device__ float g_vh [NBH * SEQ * DK];   // [bh][s][d]
__device__ float g_ctx[MROWS * D_MODEL];  // [b*S + s][h*64 + d]

// ---------------- helpers ----------------------------------------------------
__device__ __forceinline__ uint32_t f2tf(float x) {
    uint32_t u;
    asm("cvt.rna.tf32.f32 %0, %1;" : "=r"(u) : "f"(x));
    return u;
}

__device__ __forceinline__ void mma8(float* d, const uint32_t* a,
                                     uint32_t b0, uint32_t b1) {
    asm volatile(
        "mma.sync.aligned.m16n8k8.row.col.f32.tf32.tf32.f32 "
        "{%0,%1,%2,%3}, {%4,%5,%6,%7}, {%8,%9}, {%0,%1,%2,%3};"
        : "+f"(d[0]), "+f"(d[1]), "+f"(d[2]), "+f"(d[3])
        : "r"(a[0]), "r"(a[1]), "r"(a[2]), "r"(a[3]), "r"(b0), "r"(b1));
}

// ---------------- 128x128x8 fp32 tiled GEMM body (unchanged) ----------------
__device__ __forceinline__ void gemm128(
    const float* __restrict__ A, const float* __restrict__ W,
    const float* __restrict__ bias, float* __restrict__ out,
    int mode, float* As, float* Bs)
{
    const int t  = threadIdx.x;
    const int bm = blockIdx.y * 128;
    const int bn = blockIdx.x * 128;

    const int arow = t >> 1;
    const int acol = (t & 1) * 4;
    const int brow = t >> 5;
    const int bcol = (t & 31) * 4;
    const int tx = t & 15, ty = t >> 4;

    float acc[8][8];
#pragma unroll
    for (int i = 0; i < 8; ++i)
#pragma unroll
        for (int j = 0; j < 8; ++j) acc[i][j] = 0.f;

    const float* aptr = A + (size_t)(bm + arow) * 1024 + acol;
    const float* bptr = W + (size_t)brow * 1024 + bn + bcol;

    for (int k0 = 0; k0 < 1024; k0 += 8) {
        float4 av = *(const float4*)(aptr + k0);
        float4 bv = *(const float4*)(bptr + (size_t)k0 * 1024);
        __syncthreads();
        As[(acol + 0) * 128 + arow] = av.x;
        As[(acol + 1) * 128 + arow] = av.y;
        As[(acol + 2) * 128 + arow] = av.z;
        As[(acol + 3) * 128 + arow] = av.w;
        *(float4*)&Bs[brow * 128 + bcol] = bv;
        __syncthreads();
#pragma unroll
        for (int kk = 0; kk < 8; ++kk) {
            float ar[8], br[8];
            *(float4*)&ar[0] = *(float4*)&As[kk * 128 + ty * 8];
            *(float4*)&ar[4] = *(float4*)&As[kk * 128 + ty * 8 + 4];
            *(float4*)&br[0] = *(float4*)&Bs[kk * 128 + tx * 8];
            *(float4*)&br[4] = *(float4*)&Bs[kk * 128 + tx * 8 + 4];
#pragma unroll
            for (int i = 0; i < 8; ++i)
#pragma unroll
                for (int j = 0; j < 8; ++j)
                    acc[i][j] = fmaf(ar[i], br[j], acc[i][j]);
        }
    }

#pragma unroll
    for (int i = 0; i < 8; ++i) {
        const int m = bm + ty * 8 + i;
        const int b = m >> 11, s = m & 2047;
#pragma unroll
        for (int j = 0; j < 8; ++j) {
            const int n = bn + tx * 8 + j;
            float v = acc[i][j] + bias[n];
            if (mode == 0) {
                out[(size_t)m * 1024 + n] = v;
            } else {
                const int h = n >> 6, d = n & 63;
                const int bh = b * NHEAD + h;
                if (mode == 1)
                    out[((size_t)bh * SEQ + s) * DK + d] = v * 0.125f;
                else if (mode == 2)
                    out[((size_t)bh * DK + d) * SEQ + s] = v;
                else
                    out[((size_t)bh * SEQ + s) * DK + d] = v;
            }
        }
    }
}

__global__ void __launch_bounds__(256) qkv_gemm(
    const float* __restrict__ q, const float* __restrict__ k,
    const float* __restrict__ v,
    const float* __restrict__ wq, const float* __restrict__ bq,
    const float* __restrict__ wk, const float* __restrict__ bk,
    const float* __restrict__ wv, const float* __restrict__ bv)
{
    __shared__ float As[8 * 128];
    __shared__ float Bs[8 * 128];
    const int z = blockIdx.z;
    const float* A    = (z == 0) ? q  : (z == 1) ? k  : v;
    const float* W    = (z == 0) ? wq : (z == 1) ? wk : wv;
    const float* bias = (z == 0) ? bq : (z == 1) ? bk : bv;
    float* out        = (z == 0) ? g_qh : (z == 1) ? g_kT : g_vh;
    gemm128(A, W, bias, out, z + 1, As, Bs);
}

__global__ void __launch_bounds__(256) out_gemm(
    const float* __restrict__ wo, const float* __restrict__ bo,
    float* __restrict__ out)
{
    __shared__ float As[8 * 128];
    __shared__ float Bs[8 * 128];
    gemm128(g_ctx, wo, bo, out, 0, As, Bs);
}

// ---------------- attention (tf32 mma.sync) ----------------------------------
// grid (128, 32): blockIdx.y = bh, blockIdx.x = 16-query tile. 256 threads.
// smem: sc[16][SCP] | kv double buffer 2*KVBUF | qf[16][QSTR]
__global__ void __launch_bounds__(256) attn_k(float* __restrict__ attn_out)
{
    extern __shared__ float sm[];
    float*    sc  = sm;                       // 16 * SCP
    float*    kv  = sm + 16 * SCP;            // 2 * KVBUF
    float*    qf  = kv + 2 * KVBUF;           // 16 * QSTR (tf32 bits)
    uint32_t* scu = (uint32_t*)sc;
    uint32_t* kvu = (uint32_t*)kv;
    uint32_t* qfu = (uint32_t*)qf;

    const int t    = threadIdx.x;
    const int lane = t & 31;
    const int w    = t >> 5;       // warp 0..7
    const int g    = lane >> 2;    // group row 0..7
    const int t4   = lane & 3;
    const int bh   = blockIdx.y;
    const int q0   = blockIdx.x * 16;

    // ---- load Q tile -> tf32 smem ----
    {
        const float* qb = g_qh + ((size_t)bh * SEQ + q0) * DK;
        const int r = t >> 4, c4 = (t & 15) * 4;
        float4 qv = *(const float4*)&qb[r * DK + c4];
        uint4 o;
        o.x = f2tf(qv.x); o.y = f2tf(qv.y); o.z = f2tf(qv.z); o.w = f2tf(qv.w);
        *(uint4*)&qfu[r * QSTR + c4] = o;
    }
    __syncthreads();

    // ---- build Q A-fragments (16x64 = 8 k-blocks) in registers ----
    uint32_t afr[8][4];
#pragma unroll
    for (int kb = 0; kb < 8; ++kb) {
        afr[kb][0] = qfu[g       * QSTR + kb * 8 + t4];
        afr[kb][1] = qfu[(g + 8) * QSTR + kb * 8 + t4];
        afr[kb][2] = qfu[g       * QSTR + kb * 8 + t4 + 4];
        afr[kb][3] = qfu[(g + 8) * QSTR + kb * 8 + t4 + 4];
    }

    // ================= scores: S[16][2048] = Q K^T =================
    const float* kT = g_kT + (size_t)bh * DK * SEQ;
    float4 st[8];

    // prologue: chunk 0 -> buf 0
#pragma unroll
    for (int r8 = 0; r8 < 8; ++r8) {
        const int lin = r8 * 256 + t;
        const int d = lin >> 5, j4 = (lin & 31) * 4;
        st[r8] = *(const float4*)&kT[(size_t)d * SEQ + j4];
    }
#pragma unroll
    for (int r8 = 0; r8 < 8; ++r8) {
        const int lin = r8 * 256 + t;
        const int d = lin >> 5, j4 = (lin & 31) * 4;
        uint4 o;
        o.x = f2tf(st[r8].x); o.y = f2tf(st[r8].y);
        o.z = f2tf(st[r8].z); o.w = f2tf(st[r8].w);
        *(uint4*)&kvu[d * KSTR + j4] = o;
    }
    __syncthreads();

    for (int c = 0; c < 16; ++c) {
        if (c < 15) {   // prefetch next chunk into registers
#pragma unroll
            for (int r8 = 0; r8 < 8; ++r8) {
                const int lin = r8 * 256 + t;
                const int d = lin >> 5, j4 = (lin & 31) * 4;
                st[r8] = *(const float4*)&kT[(size_t)d * SEQ + (c + 1) * 128 + j4];
            }
        }
        const uint32_t* kb_base = kvu + (c & 1) * KVBUF;
        float acc0[4] = {0, 0, 0, 0}, acc1[4] = {0, 0, 0, 0};
#pragma unroll
        for (int kb = 0; kb < 8; ++kb) {
            const int jb = w * 16;
            uint32_t b00 = kb_base[(kb * 8 + t4)     * KSTR + jb + g];
            uint32_t b01 = kb_base[(kb * 8 + t4 + 4) * KSTR + jb + g];
            uint32_t b10 = kb_base[(kb * 8 + t4)     * KSTR + jb + 8 + g];
            uint32_t b11 = kb_base[(kb * 8 + t4 + 4) * KSTR + jb + 8 + g];
            mma8(acc0, afr[kb], b00, b01);
            mma8(acc1, afr[kb], b10, b11);
        }
        {   // write scores (fp32) to strip
            const int col = c * 128 + w * 16 + 2 * t4;
            sc[g       * SCP + col]     = acc0[0];
            sc[g       * SCP + col + 1] = acc0[1];
            sc[(g + 8) * SCP + col]     = acc0[2];
            sc[(g + 8) * SCP + col + 1] = acc0[3];
            sc[g       * SCP + col + 8]     = acc1[0];
            sc[g       * SCP + col + 9]     = acc1[1];
            sc[(g + 8) * SCP + col + 8]     = acc1[2];
            sc[(g + 8) * SCP + col + 9]     = acc1[3];
        }
        if (c < 15) {
#pragma unroll
            for (int r8 = 0; r8 < 8; ++r8) {
                const int lin = r8 * 256 + t;
                const int d = lin >> 5, j4 = (lin & 31) * 4;
                uint4 o;
                o.x = f2tf(st[r8].x); o.y = f2tf(st[r8].y);
                o.z = f2tf(st[r8].z); o.w = f2tf(st[r8].w);
                *(uint4*)&kvu[((c + 1) & 1) * KVBUF + d * KSTR + j4] = o;
            }
        }
        __syncthreads();
    }

    // ================= softmax (warp w owns rows 2w, 2w+1) =================
    float* attn_base = attn_out + ((size_t)bh * SEQ + q0) * SEQ;
#pragma unroll
    for (int rr = 0; rr < 2; ++rr) {
        const int i = w * 2 + rr;
        float* row = &sc[i * SCP];
        float mx = -1e30f;
#pragma unroll
        for (int kx = 0; kx < 64; ++kx) mx = fmaxf(mx, row[lane + kx * 32]);
#pragma unroll
        for (int o = 16; o; o >>= 1) mx = fmaxf(mx, __shfl_xor_sync(~0u, mx, o));
        float sum = 0.f;
#pragma unroll
        for (int kx = 0; kx < 64; ++kx) {
            const float e = __expf(row[lane + kx * 32] - mx);
            row[lane + kx * 32] = e;
            sum += e;
        }
#pragma unroll
        for (int o = 16; o; o >>= 1) sum += __shfl_xor_sync(~0u, sum, o);
        const float inv = 1.0f / sum;
        float* grow = attn_base + (size_t)i * SEQ;
        uint32_t* rowu = (uint32_t*)row;
#pragma unroll
        for (int kx = 0; kx < 16; ++kx) {
            const int j4 = (lane + kx * 32) * 4;
            float4 p = *(float4*)&row[j4];
            p.x *= inv; p.y *= inv; p.z *= inv; p.w *= inv;
            __stcs((float4*)&grow[j4], p);             // streaming: keep K/V in L2
            uint4 o;
            o.x = f2tf(p.x); o.y = f2tf(p.y); o.z = f2tf(p.z); o.w = f2tf(p.w);
            *(uint4*)&rowu[j4] = o;                    // tf32 P for P@V
        }
    }
    __syncthreads();

    // ================= ctx = P @ V (warp w owns d-block [8w, 8w+8)) ========
    const float* vb = g_vh + (size_t)bh * SEQ * DK;
    float acc[4] = {0, 0, 0, 0};

    // prologue: V chunk 0 -> buf 0
#pragma unroll
    for (int r8 = 0; r8 < 8; ++r8) {
        const int lin = r8 * 256 + t;
        const int kk = lin >> 4, d4 = (lin & 15) * 4;
        st[r8] = *(const float4*)&vb[(size_t)kk * DK + d4];
    }
#pragma unroll
    for (int r8 = 0; r8 < 8; ++r8) {
        const int lin = r8 * 256 + t;
        const int kk = lin >> 4, d4 = (lin & 15) * 4;
        uint4 o;
        o.x = f2tf(st[r8].x); o.y = f2tf(st[r8].y);
        o.z = f2tf(st[r8].z); o.w = f2tf(st[r8].w);
        *(uint4*)&kvu[kk * VSTR + d4] = o;
    }
    __syncthreads();

    for (int c = 0; c < 16; ++c) {
        if (c < 15) {
#pragma unroll
            for (int r8 = 0; r8 < 8; ++r8) {
                const int lin = r8 * 256 + t;
                const int kk = lin >> 4, d4 = (lin & 15) * 4;
                st[r8] = *(const float4*)&vb[((size_t)(c + 1) * 128 + kk) * DK + d4];
            }
        }
        const uint32_t* vb_base = kvu + (c & 1) * KVBUF;
#pragma unroll
        for (int kb = 0; kb < 16; ++kb) {
            uint32_t a[4];
            const int kc = c * 128 + kb * 8;
            a[0] = scu[g       * SCP + kc + t4];
            a[1] = scu[(g + 8) * SCP + kc + t4];
            a[2] = scu[g       * SCP + kc + t4 + 4];
            a[3] = scu[(g + 8) * SCP + kc + t4 + 4];
            uint32_t b0 = vb_base[(kb * 8 + t4)     * VSTR + w * 8 + g];
            uint32_t b1 = vb_base[(kb * 8 + t4 + 4) * VSTR + w * 8 + g];
            mma8(acc, a, b0, b1);
        }
        if (c < 15) {
#pragma unroll
            for (int r8 = 0; r8 < 8; ++r8) {
                const int lin = r8 * 256 + t;
                const int kk = lin >> 4, d4 = (lin & 15) * 4;
                uint4 o;
                o.x = f2tf(st[r8].x); o.y = f2tf(st[r8].y);
                o.z = f2tf(st[r8].z); o.w = f2tf(st[r8].w);
                *(uint4*)&kvu[((c + 1) & 1) * KVBUF + kk * VSTR + d4] = o;
            }
        }
        __syncthreads();
    }

    // ctx layout [b*S+s][h*64+d]; thread writes rows g, g+8; cols 8w+2t4(+1)
    const int b = bh >> 4, h = bh & 15;
    float* cbase = g_ctx + ((size_t)b * SEQ + q0) * D_MODEL + h * DK + w * 8;
    *(float2*)&cbase[(size_t)g       * D_MODEL + 2 * t4] = make_float2(acc[0], acc[1]);
    *(float2*)&cbase[(size_t)(g + 8) * D_MODEL + 2 * t4] = make_float2(acc[2], acc[3]);
}

// ---------------- launch -----------------------------------------------------
extern "C" void kernel_launch(void* const* d_in, const int* in_sizes, int n_in,
                              void* d_out, int out_size)
{
    (void)in_sizes; (void)n_in; (void)out_size;
    const float* q  = (const float*)d_in[0];
    const float* k  = (const float*)d_in[1];
    const float* v  = (const float*)d_in[2];
    const float* wq = (const float*)d_in[3];
    const float* bq = (const float*)d_in[4];
    const float* wk = (const float*)d_in[5];
    const float* bk = (const float*)d_in[6];
    const float* wv = (const float*)d_in[7];
    const float* bv = (const float*)d_in[8];
    const float* wo = (const float*)d_in[9];
    const float* bo = (const float*)d_in[10];

    float* out  = (float*)d_out;                       // [B,S,D]
    float* attn = out + (size_t)MROWS * D_MODEL;       // [B,H,S,S]

    const int smem = (16 * SCP + 2 * KVBUF + 16 * QSTR) * 4;  // 209408 B
    cudaFuncSetAttribute(attn_k, cudaFuncAttributeMaxDynamicSharedMemorySize, smem);

    qkv_gemm<<<dim3(8, 32, 3), 256>>>(q, k, v, wq, bq, wk, bk, wv, bv);
    attn_k<<<dim3(128, 32), 256, smem>>>(attn);
    out_gemm<<<dim3(8, 32), 256>>>(wo, bo, out);
}

// round 3
// speedup vs baseline: 2.3151x; 1.3885x over previous
#include <cuda_runtime.h>
#include <cstdint>

#define D_MODEL 1024
#define NHEAD   16
#define DK      64
#define BB      2
#define SEQ     2048
#define MROWS   (BB * SEQ)   // 4096
#define NBH     (BB * NHEAD) // 32

// padded smem strides (floats) — chosen for conflict-free mma fragment LDS
#define SCP   2052           // score strip row stride (2048 + 4)
#define KSTR  136            // K chunk: [64 d][128 keys] stride (mod32 = 8)
#define VSTR  72             // V chunk: [128 keys][64 d] stride (mod32 = 8)
#define QSTR  68             // Q tile stride (mod32 = 4)
#define KVBUF 9216           // per double-buffer (max of 64*136, 128*72)

// projection GEMM smem strides
#define ASTR  20             // A tile [m][k] stride (mod32 = 20 -> frag conflict-free)
#define BSTR  136            // W tile [k][n] stride (mod32 = 8  -> frag conflict-free)

// ---------------- scratch (device globals; allocation-free rule) ------------
__device__ float g_qh [NBH * SEQ * DK];   // [bh][s][d], pre-scaled by 1/8
__device__ float g_kT [NBH * DK * SEQ];   // [bh][d][s]  (transposed K)
__device__ float g_vh [NBH * SEQ * DK];   // [bh][s][d]
__device__ float g_ctx[MROWS * D_MODEL];  // [b*S + s][h*64 + d]

// ---------------- helpers ----------------------------------------------------
__device__ __forceinline__ uint32_t f2tf(float x) {
    uint32_t u;
    asm("cvt.rna.tf32.f32 %0, %1;" : "=r"(u) : "f"(x));
    return u;
}

__device__ __forceinline__ void mma8(float* d, const uint32_t* a,
                                     uint32_t b0, uint32_t b1) {
    asm volatile(
        "mma.sync.aligned.m16n8k8.row.col.f32.tf32.tf32.f32 "
        "{%0,%1,%2,%3}, {%4,%5,%6,%7}, {%8,%9}, {%0,%1,%2,%3};"
        : "+f"(d[0]), "+f"(d[1]), "+f"(d[2]), "+f"(d[3])
        : "r"(a[0]), "r"(a[1]), "r"(a[2]), "r"(a[3]), "r"(b0), "r"(b1));
}

// ---------------- tf32 tensor GEMM: C[4096,1024] = A @ W + bias --------------
// CTA tile 128x128, kt=16, 256 threads = 8 warps in 4(m) x 2(n).
// Epilogue modes: 0 plain row-major; 1 qh (*0.125); 2 kT; 3 vh.
__device__ __forceinline__ void gemm_tf32(
    const float* __restrict__ A, const float* __restrict__ W,
    const float* __restrict__ bias, float* __restrict__ out,
    int mode, uint32_t* As, uint32_t* Bs)   // As: 2*128*ASTR, Bs: 2*16*BSTR
{
    const int t    = threadIdx.x;
    const int lane = t & 31;
    const int w    = t >> 5;
    const int g    = lane >> 2;
    const int t4   = lane & 3;
    const int bm   = blockIdx.y * 128;
    const int bn   = blockIdx.x * 128;
    const int wm   = (w >> 1) * 32;       // warp m offset (4 warps)
    const int wn   = (w & 1) * 64;        // warp n offset (2 warps)

    // load indices
    const int a_m = t >> 1, a_c = (t & 1) * 8;     // A: row a_m, cols a_c..a_c+7
    const int w_k = t >> 4, w_c = (t & 15) * 8;    // W: row w_k, cols w_c..w_c+7

    const float* aptr = A + (size_t)(bm + a_m) * 1024 + a_c;
    const float* wptr = W + (size_t)w_k * 1024 + bn + w_c;

    float acc[2][8][4];
#pragma unroll
    for (int mt = 0; mt < 2; ++mt)
#pragma unroll
        for (int nt = 0; nt < 8; ++nt)
#pragma unroll
            for (int i = 0; i < 4; ++i) acc[mt][nt][i] = 0.f;

    float4 ra0, ra1, rb0, rb1;

    // prologue: tile 0 -> buf 0
    ra0 = *(const float4*)(aptr);
    ra1 = *(const float4*)(aptr + 4);
    rb0 = *(const float4*)(wptr);
    rb1 = *(const float4*)(wptr + 4);
    {
        uint32_t* a_s = As + a_m * ASTR + a_c;
        a_s[0] = f2tf(ra0.x); a_s[1] = f2tf(ra0.y); a_s[2] = f2tf(ra0.z); a_s[3] = f2tf(ra0.w);
        a_s[4] = f2tf(ra1.x); a_s[5] = f2tf(ra1.y); a_s[6] = f2tf(ra1.z); a_s[7] = f2tf(ra1.w);
        uint32_t* b_s = Bs + w_k * BSTR + w_c;
        b_s[0] = f2tf(rb0.x); b_s[1] = f2tf(rb0.y); b_s[2] = f2tf(rb0.z); b_s[3] = f2tf(rb0.w);
        b_s[4] = f2tf(rb1.x); b_s[5] = f2tf(rb1.y); b_s[6] = f2tf(rb1.z); b_s[7] = f2tf(rb1.w);
    }
    __syncthreads();

    for (int it = 0; it < 64; ++it) {
        const int buf = it & 1;
        if (it < 63) {   // prefetch next k-tile into registers
            const int k0 = (it + 1) * 16;
            ra0 = *(const float4*)(aptr + k0);
            ra1 = *(const float4*)(aptr + k0 + 4);
            rb0 = *(const float4*)(wptr + (size_t)k0 * 1024);
            rb1 = *(const float4*)(wptr + (size_t)k0 * 1024 + 4);
        }
        const uint32_t* Ab = As + buf * (128 * ASTR);
        const uint32_t* Bb = Bs + buf * (16 * BSTR);
#pragma unroll
        for (int ks = 0; ks < 2; ++ks) {
            uint32_t af[2][4];
#pragma unroll
            for (int mt = 0; mt < 2; ++mt) {
                const int r0 = wm + mt * 16 + g;
                af[mt][0] = Ab[r0       * ASTR + ks * 8 + t4];
                af[mt][1] = Ab[(r0 + 8) * ASTR + ks * 8 + t4];
                af[mt][2] = Ab[r0       * ASTR + ks * 8 + t4 + 4];
                af[mt][3] = Ab[(r0 + 8) * ASTR + ks * 8 + t4 + 4];
            }
#pragma unroll
            for (int nt = 0; nt < 8; ++nt) {
                const int nc = wn + nt * 8 + g;
                uint32_t b0 = Bb[(ks * 8 + t4)     * BSTR + nc];
                uint32_t b1 = Bb[(ks * 8 + t4 + 4) * BSTR + nc];
                mma8(acc[0][nt], af[0], b0, b1);
                mma8(acc[1][nt], af[1], b0, b1);
            }
        }
        if (it < 63) {   // store staged tile to other buffer
            uint32_t* a_s = As + (buf ^ 1) * (128 * ASTR) + a_m * ASTR + a_c;
            a_s[0] = f2tf(ra0.x); a_s[1] = f2tf(ra0.y); a_s[2] = f2tf(ra0.z); a_s[3] = f2tf(ra0.w);
            a_s[4] = f2tf(ra1.x); a_s[5] = f2tf(ra1.y); a_s[6] = f2tf(ra1.z); a_s[7] = f2tf(ra1.w);
            uint32_t* b_s = Bs + (buf ^ 1) * (16 * BSTR) + w_k * BSTR + w_c;
            b_s[0] = f2tf(rb0.x); b_s[1] = f2tf(rb0.y); b_s[2] = f2tf(rb0.z); b_s[3] = f2tf(rb0.w);
            b_s[4] = f2tf(rb1.x); b_s[5] = f2tf(rb1.y); b_s[6] = f2tf(rb1.z); b_s[7] = f2tf(rb1.w);
        }
        __syncthreads();
    }

    // ---- epilogue ----
#pragma unroll
    for (int mt = 0; mt < 2; ++mt) {
        const int m0 = bm + wm + mt * 16 + g;
#pragma unroll
        for (int nt = 0; nt < 8; ++nt) {
            const int n0 = bn + wn + nt * 8 + 2 * t4;      // even
            const float bz0 = bias[n0], bz1 = bias[n0 + 1];
            float v00 = acc[mt][nt][0] + bz0;
            float v01 = acc[mt][nt][1] + bz1;
            float v10 = acc[mt][nt][2] + bz0;
            float v11 = acc[mt][nt][3] + bz1;
            if (mode == 0) {
                *(float2*)&out[(size_t)m0 * 1024 + n0]       = make_float2(v00, v01);
                *(float2*)&out[(size_t)(m0 + 8) * 1024 + n0] = make_float2(v10, v11);
            } else {
                const int b0i = m0 >> 11, s0 = m0 & 2047;
                const int h = n0 >> 6, d = n0 & 63;
                const int bh = b0i * NHEAD + h;
                if (mode == 1) {
                    *(float2*)&out[((size_t)bh * SEQ + s0) * DK + d] =
                        make_float2(v00 * 0.125f, v01 * 0.125f);
                    *(float2*)&out[((size_t)bh * SEQ + s0 + 8) * DK + d] =
                        make_float2(v10 * 0.125f, v11 * 0.125f);
                } else if (mode == 3) {
                    *(float2*)&out[((size_t)bh * SEQ + s0) * DK + d] =
                        make_float2(v00, v01);
                    *(float2*)&out[((size_t)bh * SEQ + s0 + 8) * DK + d] =
                        make_float2(v10, v11);
                } else { // mode 2: kT [bh][d][s]
                    float* ob = out + (size_t)bh * DK * SEQ;
                    ob[(size_t)d       * SEQ + s0]     = v00;
                    ob[(size_t)(d + 1) * SEQ + s0]     = v01;
                    ob[(size_t)d       * SEQ + s0 + 8] = v10;
                    ob[(size_t)(d + 1) * SEQ + s0 + 8] = v11;
                }
            }
        }
    }
}

__global__ void __launch_bounds__(256) qkv_gemm(
    const float* __restrict__ q, const float* __restrict__ k,
    const float* __restrict__ v,
    const float* __restrict__ wq, const float* __restrict__ bq,
    const float* __restrict__ wk, const float* __restrict__ bk,
    const float* __restrict__ wv, const float* __restrict__ bv)
{
    __shared__ uint32_t As[2 * 128 * ASTR];
    __shared__ uint32_t Bs[2 * 16 * BSTR];
    const int z = blockIdx.z;
    const float* A    = (z == 0) ? q  : (z == 1) ? k  : v;
    const float* W    = (z == 0) ? wq : (z == 1) ? wk : wv;
    const float* bias = (z == 0) ? bq : (z == 1) ? bk : bv;
    float* out        = (z == 0) ? g_qh : (z == 1) ? g_kT : g_vh;
    gemm_tf32(A, W, bias, out, z + 1, As, Bs);
}

__global__ void __launch_bounds__(256) out_gemm(
    const float* __restrict__ wo, const float* __restrict__ bo,
    float* __restrict__ out)
{
    __shared__ uint32_t As[2 * 128 * ASTR];
    __shared__ uint32_t Bs[2 * 16 * BSTR];
    gemm_tf32(g_ctx, wo, bo, out, 0, As, Bs);
}

// ---------------- attention (tf32 mma.sync) — unchanged from R2 --------------
__global__ void __launch_bounds__(256) attn_k(float* __restrict__ attn_out)
{
    extern __shared__ float sm[];
    float*    sc  = sm;                       // 16 * SCP
    float*    kv  = sm + 16 * SCP;            // 2 * KVBUF
    float*    qf  = kv + 2 * KVBUF;           // 16 * QSTR (tf32 bits)
    uint32_t* scu = (uint32_t*)sc;
    uint32_t* kvu = (uint32_t*)kv;
    uint32_t* qfu = (uint32_t*)qf;

    const int t    = threadIdx.x;
    const int lane = t & 31;
    const int w    = t >> 5;
    const int g    = lane >> 2;
    const int t4   = lane & 3;
    const int bh   = blockIdx.y;
    const int q0   = blockIdx.x * 16;

    {
        const float* qb = g_qh + ((size_t)bh * SEQ + q0) * DK;
        const int r = t >> 4, c4 = (t & 15) * 4;
        float4 qv = *(const float4*)&qb[r * DK + c4];
        uint4 o;
        o.x = f2tf(qv.x); o.y = f2tf(qv.y); o.z = f2tf(qv.z); o.w = f2tf(qv.w);
        *(uint4*)&qfu[r * QSTR + c4] = o;
    }
    __syncthreads();

    uint32_t afr[8][4];
#pragma unroll
    for (int kb = 0; kb < 8; ++kb) {
        afr[kb][0] = qfu[g       * QSTR + kb * 8 + t4];
        afr[kb][1] = qfu[(g + 8) * QSTR + kb * 8 + t4];
        afr[kb][2] = qfu[g       * QSTR + kb * 8 + t4 + 4];
        afr[kb][3] = qfu[(g + 8) * QSTR + kb * 8 + t4 + 4];
    }

    const float* kT = g_kT + (size_t)bh * DK * SEQ;
    float4 st[8];

#pragma unroll
    for (int r8 = 0; r8 < 8; ++r8) {
        const int lin = r8 * 256 + t;
        const int d = lin >> 5, j4 = (lin & 31) * 4;
        st[r8] = *(const float4*)&kT[(size_t)d * SEQ + j4];
    }
#pragma unroll
    for (int r8 = 0; r8 < 8; ++r8) {
        const int lin = r8 * 256 + t;
        const int d = lin >> 5, j4 = (lin & 31) * 4;
        uint4 o;
        o.x = f2tf(st[r8].x); o.y = f2tf(st[r8].y);
        o.z = f2tf(st[r8].z); o.w = f2tf(st[r8].w);
        *(uint4*)&kvu[d * KSTR + j4] = o;
    }
    __syncthreads();

    for (int c = 0; c < 16; ++c) {
        if (c < 15) {
#pragma unroll
            for (int r8 = 0; r8 < 8; ++r8) {
                const int lin = r8 * 256 + t;
                const int d = lin >> 5, j4 = (lin & 31) * 4;
                st[r8] = *(const float4*)&kT[(size_t)d * SEQ + (c + 1) * 128 + j4];
            }
        }
        const uint32_t* kb_base = kvu + (c & 1) * KVBUF;
        float acc0[4] = {0, 0, 0, 0}, acc1[4] = {0, 0, 0, 0};
#pragma unroll
        for (int kb = 0; kb < 8; ++kb) {
            const int jb = w * 16;
            uint32_t b00 = kb_base[(kb * 8 + t4)     * KSTR + jb + g];
            uint32_t b01 = kb_base[(kb * 8 + t4 + 4) * KSTR + jb + g];
            uint32_t b10 = kb_base[(kb * 8 + t4)     * KSTR + jb + 8 + g];
            uint32_t b11 = kb_base[(kb * 8 + t4 + 4) * KSTR + jb + 8 + g];
            mma8(acc0, afr[kb], b00, b01);
            mma8(acc1, afr[kb], b10, b11);
        }
        {
            const int col = c * 128 + w * 16 + 2 * t4;
            sc[g       * SCP + col]     = acc0[0];
            sc[g       * SCP + col + 1] = acc0[1];
            sc[(g + 8) * SCP + col]     = acc0[2];
            sc[(g + 8) * SCP + col + 1] = acc0[3];
            sc[g       * SCP + col + 8]     = acc1[0];
            sc[g       * SCP + col + 9]     = acc1[1];
            sc[(g + 8) * SCP + col + 8]     = acc1[2];
            sc[(g + 8) * SCP + col + 9]     = acc1[3];
        }
        if (c < 15) {
#pragma unroll
            for (int r8 = 0; r8 < 8; ++r8) {
                const int lin = r8 * 256 + t;
                const int d = lin >> 5, j4 = (lin & 31) * 4;
                uint4 o;
                o.x = f2tf(st[r8].x); o.y = f2tf(st[r8].y);
                o.z = f2tf(st[r8].z); o.w = f2tf(st[r8].w);
                *(uint4*)&kvu[((c + 1) & 1) * KVBUF + d * KSTR + j4] = o;
            }
        }
        __syncthreads();
    }

    float* attn_base = attn_out + ((size_t)bh * SEQ + q0) * SEQ;
#pragma unroll
    for (int rr = 0; rr < 2; ++rr) {
        const int i = w * 2 + rr;
        float* row = &sc[i * SCP];
        float mx = -1e30f;
#pragma unroll
        for (int kx = 0; kx < 64; ++kx) mx = fmaxf(mx, row[lane + kx * 32]);
#pragma unroll
        for (int o = 16; o; o >>= 1) mx = fmaxf(mx, __shfl_xor_sync(~0u, mx, o));
        float sum = 0.f;
#pragma unroll
        for (int kx = 0; kx < 64; ++kx) {
            const float e = __expf(row[lane + kx * 32] - mx);
            row[lane + kx * 32] = e;
            sum += e;
        }
#pragma unroll
        for (int o = 16; o; o >>= 1) sum += __shfl_xor_sync(~0u, sum, o);
        const float inv = 1.0f / sum;
        float* grow = attn_base + (size_t)i * SEQ;
        uint32_t* rowu = (uint32_t*)row;
#pragma unroll
        for (int kx = 0; kx < 16; ++kx) {
            const int j4 = (lane + kx * 32) * 4;
            float4 p = *(float4*)&row[j4];
            p.x *= inv; p.y *= inv; p.z *= inv; p.w *= inv;
            __stcs((float4*)&grow[j4], p);
            uint4 o;
            o.x = f2tf(p.x); o.y = f2tf(p.y); o.z = f2tf(p.z); o.w = f2tf(p.w);
            *(uint4*)&rowu[j4] = o;
        }
    }
    __syncthreads();

    const float* vb = g_vh + (size_t)bh * SEQ * DK;
    float acc[4] = {0, 0, 0, 0};

#pragma unroll
    for (int r8 = 0; r8 < 8; ++r8) {
        const int lin = r8 * 256 + t;
        const int kk = lin >> 4, d4 = (lin & 15) * 4;
        st[r8] = *(const float4*)&vb[(size_t)kk * DK + d4];
    }
#pragma unroll
    for (int r8 = 0; r8 < 8; ++r8) {
        const int lin = r8 * 256 + t;
        const int kk = lin >> 4, d4 = (lin & 15) * 4;
        uint4 o;
        o.x = f2tf(st[r8].x); o.y = f2tf(st[r8].y);
        o.z = f2tf(st[r8].z); o.w = f2tf(st[r8].w);
        *(uint4*)&kvu[kk * VSTR + d4] = o;
    }
    __syncthreads();

    for (int c = 0; c < 16; ++c) {
        if (c < 15) {
#pragma unroll
            for (int r8 = 0; r8 < 8; ++r8) {
                const int lin = r8 * 256 + t;
                const int kk = lin >> 4, d4 = (lin & 15) * 4;
                st[r8] = *(const float4*)&vb[((size_t)(c + 1) * 128 + kk) * DK + d4];
            }
        }
        const uint32_t* vb_base = kvu + (c & 1) * KVBUF;
#pragma unroll
        for (int kb = 0; kb < 16; ++kb) {
            uint32_t a[4];
            const int kc = c * 128 + kb * 8;
            a[0] = scu[g       * SCP + kc + t4];
            a[1] = scu[(g + 8) * SCP + kc + t4];
            a[2] = scu[g       * SCP + kc + t4 + 4];
            a[3] = scu[(g + 8) * SCP + kc + t4 + 4];
            uint32_t b0 = vb_base[(kb * 8 + t4)     * VSTR + w * 8 + g];
            uint32_t b1 = vb_base[(kb * 8 + t4 + 4) * VSTR + w * 8 + g];
            mma8(acc, a, b0, b1);
        }
        if (c < 15) {
#pragma unroll
            for (int r8 = 0; r8 < 8; ++r8) {
                const int lin = r8 * 256 + t;
                const int kk = lin >> 4, d4 = (lin & 15) * 4;
                uint4 o;
                o.x = f2tf(st[r8].x); o.y = f2tf(st[r8].y);
                o.z = f2tf(st[r8].z); o.w = f2tf(st[r8].w);
                *(uint4*)&kvu[((c + 1) & 1) * KVBUF + kk * VSTR + d4] = o;
            }
        }
        __syncthreads();
    }

    const int b = bh >> 4, h = bh & 15;
    float* cbase = g_ctx + ((size_t)b * SEQ + q0) * D_MODEL + h * DK + w * 8;
    *(float2*)&cbase[(size_t)g       * D_MODEL + 2 * t4] = make_float2(acc[0], acc[1]);
    *(float2*)&cbase[(size_t)(g + 8) * D_MODEL + 2 * t4] = make_float2(acc[2], acc[3]);
}

// ---------------- launch -----------------------------------------------------
extern "C" void kernel_launch(void* const* d_in, const int* in_sizes, int n_in,
                              void* d_out, int out_size)
{
    (void)in_sizes; (void)n_in; (void)out_size;
    const float* q  = (const float*)d_in[0];
    const float* k  = (const float*)d_in[1];
    const float* v  = (const float*)d_in[2];
    const float* wq = (const float*)d_in[3];
    const float* bq = (const float*)d_in[4];
    const float* wk = (const float*)d_in[5];
    const float* bk = (const float*)d_in[6];
    const float* wv = (const float*)d_in[7];
    const float* bv = (const float*)d_in[8];
    const float* wo = (const float*)d_in[9];
    const float* bo = (const float*)d_in[10];

    float* out  = (float*)d_out;                       // [B,S,D]
    float* attn = out + (size_t)MROWS * D_MODEL;       // [B,H,S,S]

    const int smem = (16 * SCP + 2 * KVBUF + 16 * QSTR) * 4;  // 209408 B
    cudaFuncSetAttribute(attn_k, cudaFuncAttributeMaxDynamicSharedMemorySize, smem);

    qkv_gemm<<<dim3(8, 32, 3), 256>>>(q, k, v, wq, bq, wk, bk, wv, bv);
    attn_k<<<dim3(128, 32), 256, smem>>>(attn);
    out_gemm<<<dim3(8, 32), 256>>>(wo, bo, out);
}

// round 4
// speedup vs baseline: 2.4780x; 1.0704x over previous
#include <cuda_runtime.h>
#include <cstdint>

#define D_MODEL 1024
#define NHEAD   16
#define DK      64
#define BB      2
#define SEQ     2048
#define MROWS   (BB * SEQ)   // 4096
#define NBH     (BB * NHEAD) // 32

// padded smem strides (in 4B units)
#define SCP   2052           // score strip row stride
#define KSTR  136            // K chunk [64 d][128 keys]
#define VSTR  72             // V chunk [128 keys][64 d]
#define QSTR  68             // Q tile
#define KVBUF 9216

#define ASTR  20             // gemm A tile stride
#define BSTR  136            // gemm W tile stride

// ---------------- scratch (device globals) -----------------------------------
// tf32-converted inputs / weights
__device__ uint32_t g_qin[MROWS * D_MODEL];
__device__ uint32_t g_kin[MROWS * D_MODEL];
__device__ uint32_t g_vin[MROWS * D_MODEL];
__device__ uint32_t g_wqc[D_MODEL * D_MODEL];
__device__ uint32_t g_wkc[D_MODEL * D_MODEL];
__device__ uint32_t g_wvc[D_MODEL * D_MODEL];
__device__ uint32_t g_woc[D_MODEL * D_MODEL];
// projected tensors, stored as tf32 bits
__device__ uint32_t g_qh [NBH * SEQ * DK];   // [bh][s][d], pre-scaled by 1/8
__device__ uint32_t g_kT [NBH * DK * SEQ];   // [bh][d][s]
__device__ uint32_t g_vh [NBH * SEQ * DK];   // [bh][s][d]
__device__ uint32_t g_ctx[MROWS * D_MODEL];  // [b*S+s][h*64+d], tf32 bits

// ---------------- helpers ----------------------------------------------------
__device__ __forceinline__ uint32_t f2tf(float x) {
    uint32_t u;
    asm("cvt.rna.tf32.f32 %0, %1;" : "=r"(u) : "f"(x));
    return u;
}

__device__ __forceinline__ void mma8(float* d, const uint32_t* a,
                                     uint32_t b0, uint32_t b1) {
    asm volatile(
        "mma.sync.aligned.m16n8k8.row.col.f32.tf32.tf32.f32 "
        "{%0,%1,%2,%3}, {%4,%5,%6,%7}, {%8,%9}, {%0,%1,%2,%3};"
        : "+f"(d[0]), "+f"(d[1]), "+f"(d[2]), "+f"(d[3])
        : "r"(a[0]), "r"(a[1]), "r"(a[2]), "r"(a[3]), "r"(b0), "r"(b1));
}

// ---------------- pre-convert fp32 -> tf32 bits -------------------------------
__global__ void __launch_bounds__(256) cvt_inputs(
    const float* __restrict__ q, const float* __restrict__ k,
    const float* __restrict__ v)
{
    const float* src = (blockIdx.y == 0) ? q : (blockIdx.y == 1) ? k : v;
    uint32_t* dst = (blockIdx.y == 0) ? g_qin : (blockIdx.y == 1) ? g_kin : g_vin;
    const int i = (blockIdx.x * 256 + threadIdx.x) * 4;
    float4 f = *(const float4*)&src[i];
    uint4 o;
    o.x = f2tf(f.x); o.y = f2tf(f.y); o.z = f2tf(f.z); o.w = f2tf(f.w);
    *(uint4*)&dst[i] = o;
}

__global__ void __launch_bounds__(256) cvt_weights(
    const float* __restrict__ wq, const float* __restrict__ wk,
    const float* __restrict__ wv, const float* __restrict__ wo)
{
    const float* src = (blockIdx.y == 0) ? wq : (blockIdx.y == 1) ? wk
                     : (blockIdx.y == 2) ? wv : wo;
    uint32_t* dst = (blockIdx.y == 0) ? g_wqc : (blockIdx.y == 1) ? g_wkc
                  : (blockIdx.y == 2) ? g_wvc : g_woc;
    const int i = (blockIdx.x * 256 + threadIdx.x) * 4;
    float4 f = *(const float4*)&src[i];
    uint4 o;
    o.x = f2tf(f.x); o.y = f2tf(f.y); o.z = f2tf(f.z); o.w = f2tf(f.w);
    *(uint4*)&dst[i] = o;
}

// ---------------- tf32 tensor GEMM (operands pre-converted) ------------------
// C[4096,1024] = A @ W + bias. CTA 128x128, kt=16, 256 thr (8 warps 4m x 2n).
// mode: 0 -> fp32 row-major out; 1 -> g_qh tf32 (*0.125); 2 -> g_kT tf32;
//       3 -> g_vh tf32.
__device__ __forceinline__ void gemm_tf32(
    const uint32_t* __restrict__ A, const uint32_t* __restrict__ W,
    const float* __restrict__ bias, void* __restrict__ outp,
    int mode, uint32_t* As, uint32_t* Bs)
{
    const int t    = threadIdx.x;
    const int lane = t & 31;
    const int w    = t >> 5;
    const int g    = lane >> 2;
    const int t4   = lane & 3;
    const int bm   = blockIdx.y * 128;
    const int bn   = blockIdx.x * 128;
    const int wm   = (w >> 1) * 32;
    const int wn   = (w & 1) * 64;

    const int a_m = t >> 1, a_c = (t & 1) * 8;
    const int w_k = t >> 4, w_c = (t & 15) * 8;

    const uint32_t* aptr = A + (size_t)(bm + a_m) * 1024 + a_c;
    const uint32_t* wptr = W + (size_t)w_k * 1024 + bn + w_c;

    float acc[2][8][4];
#pragma unroll
    for (int mt = 0; mt < 2; ++mt)
#pragma unroll
        for (int nt = 0; nt < 8; ++nt)
#pragma unroll
            for (int i = 0; i < 4; ++i) acc[mt][nt][i] = 0.f;

    uint4 ra0, ra1, rb0, rb1;

    ra0 = *(const uint4*)(aptr);
    ra1 = *(const uint4*)(aptr + 4);
    rb0 = *(const uint4*)(wptr);
    rb1 = *(const uint4*)(wptr + 4);
    *(uint4*)&As[a_m * ASTR + a_c]     = ra0;
    *(uint4*)&As[a_m * ASTR + a_c + 4] = ra1;
    *(uint4*)&Bs[w_k * BSTR + w_c]     = rb0;
    *(uint4*)&Bs[w_k * BSTR + w_c + 4] = rb1;
    __syncthreads();

    for (int it = 0; it < 64; ++it) {
        const int buf = it & 1;
        if (it < 63) {
            const int k0 = (it + 1) * 16;
            ra0 = *(const uint4*)(aptr + k0);
            ra1 = *(const uint4*)(aptr + k0 + 4);
            rb0 = *(const uint4*)(wptr + (size_t)k0 * 1024);
            rb1 = *(const uint4*)(wptr + (size_t)k0 * 1024 + 4);
        }
        const uint32_t* Ab = As + buf * (128 * ASTR);
        const uint32_t* Bb = Bs + buf * (16 * BSTR);
#pragma unroll
        for (int ks = 0; ks < 2; ++ks) {
            uint32_t af[2][4];
#pragma unroll
            for (int mt = 0; mt < 2; ++mt) {
                const int r0 = wm + mt * 16 + g;
                af[mt][0] = Ab[r0       * ASTR + ks * 8 + t4];
                af[mt][1] = Ab[(r0 + 8) * ASTR + ks * 8 + t4];
                af[mt][2] = Ab[r0       * ASTR + ks * 8 + t4 + 4];
                af[mt][3] = Ab[(r0 + 8) * ASTR + ks * 8 + t4 + 4];
            }
#pragma unroll
            for (int nt = 0; nt < 8; ++nt) {
                const int nc = wn + nt * 8 + g;
                uint32_t b0 = Bb[(ks * 8 + t4)     * BSTR + nc];
                uint32_t b1 = Bb[(ks * 8 + t4 + 4) * BSTR + nc];
                mma8(acc[0][nt], af[0], b0, b1);
                mma8(acc[1][nt], af[1], b0, b1);
            }
        }
        if (it < 63) {
            uint32_t* a_s = As + (buf ^ 1) * (128 * ASTR) + a_m * ASTR + a_c;
            *(uint4*)(a_s)     = ra0;
            *(uint4*)(a_s + 4) = ra1;
            uint32_t* b_s = Bs + (buf ^ 1) * (16 * BSTR) + w_k * BSTR + w_c;
            *(uint4*)(b_s)     = rb0;
            *(uint4*)(b_s + 4) = rb1;
        }
        __syncthreads();
    }

    // ---- epilogue ----
#pragma unroll
    for (int mt = 0; mt < 2; ++mt) {
        const int m0 = bm + wm + mt * 16 + g;
#pragma unroll
        for (int nt = 0; nt < 8; ++nt) {
            const int n0 = bn + wn + nt * 8 + 2 * t4;
            const float bz0 = bias[n0], bz1 = bias[n0 + 1];
            float v00 = acc[mt][nt][0] + bz0;
            float v01 = acc[mt][nt][1] + bz1;
            float v10 = acc[mt][nt][2] + bz0;
            float v11 = acc[mt][nt][3] + bz1;
            if (mode == 0) {
                float* out = (float*)outp;
                *(float2*)&out[(size_t)m0 * 1024 + n0]       = make_float2(v00, v01);
                *(float2*)&out[(size_t)(m0 + 8) * 1024 + n0] = make_float2(v10, v11);
            } else {
                uint32_t* out = (uint32_t*)outp;
                const int b0i = m0 >> 11, s0 = m0 & 2047;
                const int h = n0 >> 6, d = n0 & 63;
                const int bh = b0i * NHEAD + h;
                if (mode == 1) {
                    *(uint2*)&out[((size_t)bh * SEQ + s0) * DK + d] =
                        make_uint2(f2tf(v00 * 0.125f), f2tf(v01 * 0.125f));
                    *(uint2*)&out[((size_t)bh * SEQ + s0 + 8) * DK + d] =
                        make_uint2(f2tf(v10 * 0.125f), f2tf(v11 * 0.125f));
                } else if (mode == 3) {
                    *(uint2*)&out[((size_t)bh * SEQ + s0) * DK + d] =
                        make_uint2(f2tf(v00), f2tf(v01));
                    *(uint2*)&out[((size_t)bh * SEQ + s0 + 8) * DK + d] =
                        make_uint2(f2tf(v10), f2tf(v11));
                } else { // mode 2: kT [bh][d][s]
                    uint32_t* ob = out + (size_t)bh * DK * SEQ;
                    ob[(size_t)d       * SEQ + s0]     = f2tf(v00);
                    ob[(size_t)(d + 1) * SEQ + s0]     = f2tf(v01);
                    ob[(size_t)d       * SEQ + s0 + 8] = f2tf(v10);
                    ob[(size_t)(d + 1) * SEQ + s0 + 8] = f2tf(v11);
                }
            }
        }
    }
}

__global__ void __launch_bounds__(256) qkv_gemm()
{
    __shared__ uint32_t As[2 * 128 * ASTR];
    __shared__ uint32_t Bs[2 * 16 * BSTR];
    const int z = blockIdx.z;
    const uint32_t* A = (z == 0) ? g_qin : (z == 1) ? g_kin : g_vin;
    const uint32_t* W = (z == 0) ? g_wqc : (z == 1) ? g_wkc : g_wvc;
    uint32_t* out    = (z == 0) ? g_qh : (z == 1) ? g_kT : g_vh;
    // biases passed via constant globals below
    extern __shared__ uint32_t dummy[];
    (void)dummy;
    // bias pointers are stored in a device-global table set on host side? Not
    // allowed; instead biases come through kernel params in the wrapper.
    // (This body is replaced by qkv_gemm_p below.)
    (void)A; (void)W; (void)out; (void)As; (void)Bs;
}

__global__ void __launch_bounds__(256) qkv_gemm_p(
    const float* __restrict__ bq, const float* __restrict__ bk,
    const float* __restrict__ bv)
{
    __shared__ uint32_t As[2 * 128 * ASTR];
    __shared__ uint32_t Bs[2 * 16 * BSTR];
    const int z = blockIdx.z;
    const uint32_t* A    = (z == 0) ? g_qin : (z == 1) ? g_kin : g_vin;
    const uint32_t* W    = (z == 0) ? g_wqc : (z == 1) ? g_wkc : g_wvc;
    const float*    bias = (z == 0) ? bq    : (z == 1) ? bk    : bv;
    uint32_t* out        = (z == 0) ? g_qh  : (z == 1) ? g_kT  : g_vh;
    gemm_tf32(A, W, bias, out, z + 1, As, Bs);
}

__global__ void __launch_bounds__(256) out_gemm(
    const float* __restrict__ bo, float* __restrict__ out)
{
    __shared__ uint32_t As[2 * 128 * ASTR];
    __shared__ uint32_t Bs[2 * 16 * BSTR];
    gemm_tf32(g_ctx, g_woc, bo, out, 0, As, Bs);
}

// ---------------- attention (tf32 mma.sync, pre-converted K/V/Q) -------------
__global__ void __launch_bounds__(256) attn_k(float* __restrict__ attn_out)
{
    extern __shared__ float sm[];
    float*    sc  = sm;                       // 16 * SCP (fp32 scores)
    uint32_t* kvu = (uint32_t*)(sm + 16 * SCP);   // 2 * KVBUF (tf32 bits)
    uint32_t* qfu = kvu + 2 * KVBUF;              // 16 * QSTR
    uint32_t* scu = (uint32_t*)sc;

    const int t    = threadIdx.x;
    const int lane = t & 31;
    const int w    = t >> 5;
    const int g    = lane >> 2;
    const int t4   = lane & 3;
    const int bh   = blockIdx.y;
    const int q0   = blockIdx.x * 16;

    {   // Q tile: straight bit-copy (already tf32 + scaled)
        const uint32_t* qb = g_qh + ((size_t)bh * SEQ + q0) * DK;
        const int r = t >> 4, c4 = (t & 15) * 4;
        *(uint4*)&qfu[r * QSTR + c4] = *(const uint4*)&qb[r * DK + c4];
    }
    __syncthreads();

    uint32_t afr[8][4];
#pragma unroll
    for (int kb = 0; kb < 8; ++kb) {
        afr[kb][0] = qfu[g       * QSTR + kb * 8 + t4];
        afr[kb][1] = qfu[(g + 8) * QSTR + kb * 8 + t4];
        afr[kb][2] = qfu[g       * QSTR + kb * 8 + t4 + 4];
        afr[kb][3] = qfu[(g + 8) * QSTR + kb * 8 + t4 + 4];
    }

    // ================= scores =================
    const uint32_t* kT = g_kT + (size_t)bh * DK * SEQ;
    uint4 st[8];

#pragma unroll
    for (int r8 = 0; r8 < 8; ++r8) {
        const int lin = r8 * 256 + t;
        const int d = lin >> 5, j4 = (lin & 31) * 4;
        st[r8] = *(const uint4*)&kT[(size_t)d * SEQ + j4];
    }
#pragma unroll
    for (int r8 = 0; r8 < 8; ++r8) {
        const int lin = r8 * 256 + t;
        const int d = lin >> 5, j4 = (lin & 31) * 4;
        *(uint4*)&kvu[d * KSTR + j4] = st[r8];
    }
    __syncthreads();

    for (int c = 0; c < 16; ++c) {
        if (c < 15) {
#pragma unroll
            for (int r8 = 0; r8 < 8; ++r8) {
                const int lin = r8 * 256 + t;
                const int d = lin >> 5, j4 = (lin & 31) * 4;
                st[r8] = *(const uint4*)&kT[(size_t)d * SEQ + (c + 1) * 128 + j4];
            }
        }
        const uint32_t* kb_base = kvu + (c & 1) * KVBUF;
        float acc0[4] = {0, 0, 0, 0}, acc1[4] = {0, 0, 0, 0};
#pragma unroll
        for (int kb = 0; kb < 8; ++kb) {
            const int jb = w * 16;
            uint32_t b00 = kb_base[(kb * 8 + t4)     * KSTR + jb + g];
            uint32_t b01 = kb_base[(kb * 8 + t4 + 4) * KSTR + jb + g];
            uint32_t b10 = kb_base[(kb * 8 + t4)     * KSTR + jb + 8 + g];
            uint32_t b11 = kb_base[(kb * 8 + t4 + 4) * KSTR + jb + 8 + g];
            mma8(acc0, afr[kb], b00, b01);
            mma8(acc1, afr[kb], b10, b11);
        }
        {
            const int col = c * 128 + w * 16 + 2 * t4;
            sc[g       * SCP + col]     = acc0[0];
            sc[g       * SCP + col + 1] = acc0[1];
            sc[(g + 8) * SCP + col]     = acc0[2];
            sc[(g + 8) * SCP + col + 1] = acc0[3];
            sc[g       * SCP + col + 8]     = acc1[0];
            sc[g       * SCP + col + 9]     = acc1[1];
            sc[(g + 8) * SCP + col + 8]     = acc1[2];
            sc[(g + 8) * SCP + col + 9]     = acc1[3];
        }
        if (c < 15) {
#pragma unroll
            for (int r8 = 0; r8 < 8; ++r8) {
                const int lin = r8 * 256 + t;
                const int d = lin >> 5, j4 = (lin & 31) * 4;
                *(uint4*)&kvu[((c + 1) & 1) * KVBUF + d * KSTR + j4] = st[r8];
            }
        }
        __syncthreads();
    }

    // ================= softmax =================
    float* attn_base = attn_out + ((size_t)bh * SEQ + q0) * SEQ;
#pragma unroll
    for (int rr = 0; rr < 2; ++rr) {
        const int i = w * 2 + rr;
        float* row = &sc[i * SCP];
        float mx = -1e30f;
#pragma unroll
        for (int kx = 0; kx < 64; ++kx) mx = fmaxf(mx, row[lane + kx * 32]);
#pragma unroll
        for (int o = 16; o; o >>= 1) mx = fmaxf(mx, __shfl_xor_sync(~0u, mx, o));
        float sum = 0.f;
#pragma unroll
        for (int kx = 0; kx < 64; ++kx) {
            const float e = __expf(row[lane + kx * 32] - mx);
            row[lane + kx * 32] = e;
            sum += e;
        }
#pragma unroll
        for (int o = 16; o; o >>= 1) sum += __shfl_xor_sync(~0u, sum, o);
        const float inv = 1.0f / sum;
        float* grow = attn_base + (size_t)i * SEQ;
        uint32_t* rowu = (uint32_t*)row;
#pragma unroll
        for (int kx = 0; kx < 16; ++kx) {
            const int j4 = (lane + kx * 32) * 4;
            float4 p = *(float4*)&row[j4];
            p.x *= inv; p.y *= inv; p.z *= inv; p.w *= inv;
            __stcs((float4*)&grow[j4], p);
            uint4 o;
            o.x = f2tf(p.x); o.y = f2tf(p.y); o.z = f2tf(p.z); o.w = f2tf(p.w);
            *(uint4*)&rowu[j4] = o;
        }
    }
    __syncthreads();

    // ================= ctx = P @ V =================
    const uint32_t* vb = g_vh + (size_t)bh * SEQ * DK;
    float acc[4] = {0, 0, 0, 0};

#pragma unroll
    for (int r8 = 0; r8 < 8; ++r8) {
        const int lin = r8 * 256 + t;
        const int kk = lin >> 4, d4 = (lin & 15) * 4;
        st[r8] = *(const uint4*)&vb[(size_t)kk * DK + d4];
    }
#pragma unroll
    for (int r8 = 0; r8 < 8; ++r8) {
        const int lin = r8 * 256 + t;
        const int kk = lin >> 4, d4 = (lin & 15) * 4;
        *(uint4*)&kvu[kk * VSTR + d4] = st[r8];
    }
    __syncthreads();

    for (int c = 0; c < 16; ++c) {
        if (c < 15) {
#pragma unroll
            for (int r8 = 0; r8 < 8; ++r8) {
                const int lin = r8 * 256 + t;
                const int kk = lin >> 4, d4 = (lin & 15) * 4;
                st[r8] = *(const uint4*)&vb[((size_t)(c + 1) * 128 + kk) * DK + d4];
            }
        }
        const uint32_t* vb_base = kvu + (c & 1) * KVBUF;
#pragma unroll
        for (int kb = 0; kb < 16; ++kb) {
            uint32_t a[4];
            const int kc = c * 128 + kb * 8;
            a[0] = scu[g       * SCP + kc + t4];
            a[1] = scu[(g + 8) * SCP + kc + t4];
            a[2] = scu[g       * SCP + kc + t4 + 4];
            a[3] = scu[(g + 8) * SCP + kc + t4 + 4];
            uint32_t b0 = vb_base[(kb * 8 + t4)     * VSTR + w * 8 + g];
            uint32_t b1 = vb_base[(kb * 8 + t4 + 4) * VSTR + w * 8 + g];
            mma8(acc, a, b0, b1);
        }
        if (c < 15) {
#pragma unroll
            for (int r8 = 0; r8 < 8; ++r8) {
                const int lin = r8 * 256 + t;
                const int kk = lin >> 4, d4 = (lin & 15) * 4;
                *(uint4*)&kvu[((c + 1) & 1) * KVBUF + kk * VSTR + d4] = st[r8];
            }
        }
        __syncthreads();
    }

    // ctx as tf32 bits for out_gemm
    const int b = bh >> 4, h = bh & 15;
    uint32_t* cbase = g_ctx + ((size_t)b * SEQ + q0) * D_MODEL + h * DK + w * 8;
    *(uint2*)&cbase[(size_t)g       * D_MODEL + 2 * t4] =
        make_uint2(f2tf(acc[0]), f2tf(acc[1]));
    *(uint2*)&cbase[(size_t)(g + 8) * D_MODEL + 2 * t4] =
        make_uint2(f2tf(acc[2]), f2tf(acc[3]));
}

// ---------------- launch -----------------------------------------------------
extern "C" void kernel_launch(void* const* d_in, const int* in_sizes, int n_in,
                              void* d_out, int out_size)
{
    (void)in_sizes; (void)n_in; (void)out_size;
    const float* q  = (const float*)d_in[0];
    const float* k  = (const float*)d_in[1];
    const float* v  = (const float*)d_in[2];
    const float* wq = (const float*)d_in[3];
    const float* bq = (const float*)d_in[4];
    const float* wk = (const float*)d_in[5];
    const float* bk = (const float*)d_in[6];
    const float* wv = (const float*)d_in[7];
    const float* bv = (const float*)d_in[8];
    const float* wo = (const float*)d_in[9];
    const float* bo = (const float*)d_in[10];

    float* out  = (float*)d_out;                       // [B,S,D]
    float* attn = out + (size_t)MROWS * D_MODEL;       // [B,H,S,S]

    const int smem = (16 * SCP + 2 * KVBUF + 16 * QSTR) * 4;  // 209408 B
    cudaFuncSetAttribute(attn_k, cudaFuncAttributeMaxDynamicSharedMemorySize, smem);

    cvt_inputs <<<dim3(MROWS * D_MODEL / (256 * 4), 3), 256>>>(q, k, v);
    cvt_weights<<<dim3(D_MODEL * D_MODEL / (256 * 4), 4), 256>>>(wq, wk, wv, wo);
    qkv_gemm_p<<<dim3(8, 32, 3), 256>>>(bq, bk, bv);
    attn_k<<<dim3(128, 32), 256, smem>>>(attn);
    out_gemm<<<dim3(8, 32), 256>>>(bo, out);
}

// round 6
// speedup vs baseline: 2.8099x; 1.1340x over previous
#include <cuda_runtime.h>
#include <cstdint>

#define D_MODEL 1024
#define NHEAD   16
#define DK      64
#define BB      2
#define SEQ     2048
#define MROWS   (BB * SEQ)   // 4096
#define NBH     (BB * NHEAD) // 32

// attention tiling
#define QROWS 64
#define CHUNK 128
#define NCH   (SEQ / CHUNK)  // 16

// padded smem strides (u32 units)
#define KSTR  136            // K chunk [64 d][128 keys]
#define VSTR  72             // V chunk [128 keys][64 d]
#define QSTR  68             // Q tile [64 rows][64 d]
#define PSTR  132            // P chunk [64 rows][128 keys]

// projection GEMM strides
#define ASTR  20
#define BSTR  136

// ---------------- scratch (device globals) -----------------------------------
__device__ uint32_t g_qin[MROWS * D_MODEL];
__device__ uint32_t g_kin[MROWS * D_MODEL];
__device__ uint32_t g_vin[MROWS * D_MODEL];
__device__ uint32_t g_wqc[D_MODEL * D_MODEL];
__device__ uint32_t g_wkc[D_MODEL * D_MODEL];
__device__ uint32_t g_wvc[D_MODEL * D_MODEL];
__device__ uint32_t g_woc[D_MODEL * D_MODEL];
__device__ uint32_t g_qh [NBH * SEQ * DK];   // [bh][s][d] tf32, pre-scaled 1/8
__device__ uint32_t g_kT [NBH * DK * SEQ];   // [bh][d][s] tf32
__device__ uint32_t g_vh [NBH * SEQ * DK];   // [bh][s][d] tf32
__device__ uint32_t g_ctx[MROWS * D_MODEL];  // [b*S+s][h*64+d] tf32

// ---------------- helpers ----------------------------------------------------
__device__ __forceinline__ uint32_t f2tf(float x) {
    uint32_t u;
    asm("cvt.rna.tf32.f32 %0, %1;" : "=r"(u) : "f"(x));
    return u;
}

__device__ __forceinline__ void mma8(float* d, const uint32_t* a,
                                     uint32_t b0, uint32_t b1) {
    asm volatile(
        "mma.sync.aligned.m16n8k8.row.col.f32.tf32.tf32.f32 "
        "{%0,%1,%2,%3}, {%4,%5,%6,%7}, {%8,%9}, {%0,%1,%2,%3};"
        : "+f"(d[0]), "+f"(d[1]), "+f"(d[2]), "+f"(d[3])
        : "r"(a[0]), "r"(a[1]), "r"(a[2]), "r"(a[3]), "r"(b0), "r"(b1));
}

__device__ __forceinline__ void ldsm4(uint32_t* r, uint32_t saddr) {
    asm volatile(
        "ldmatrix.sync.aligned.m8n8.x4.shared.b16 {%0,%1,%2,%3}, [%4];"
        : "=r"(r[0]), "=r"(r[1]), "=r"(r[2]), "=r"(r[3]) : "r"(saddr));
}

// ---------------- pre-convert fp32 -> tf32 bits -------------------------------
__global__ void __launch_bounds__(256) cvt_inputs(
    const float* __restrict__ q, const float* __restrict__ k,
    const float* __restrict__ v)
{
    const float* src = (blockIdx.y == 0) ? q : (blockIdx.y == 1) ? k : v;
    uint32_t* dst = (blockIdx.y == 0) ? g_qin : (blockIdx.y == 1) ? g_kin : g_vin;
    const int i = (blockIdx.x * 256 + threadIdx.x) * 4;
    float4 f = *(const float4*)&src[i];
    uint4 o;
    o.x = f2tf(f.x); o.y = f2tf(f.y); o.z = f2tf(f.z); o.w = f2tf(f.w);
    *(uint4*)&dst[i] = o;
}

__global__ void __launch_bounds__(256) cvt_weights(
    const float* __restrict__ wq, const float* __restrict__ wk,
    const float* __restrict__ wv, const float* __restrict__ wo)
{
    const float* src = (blockIdx.y == 0) ? wq : (blockIdx.y == 1) ? wk
                     : (blockIdx.y == 2) ? wv : wo;
    uint32_t* dst = (blockIdx.y == 0) ? g_wqc : (blockIdx.y == 1) ? g_wkc
                  : (blockIdx.y == 2) ? g_wvc : g_woc;
    const int i = (blockIdx.x * 256 + threadIdx.x) * 4;
    float4 f = *(const float4*)&src[i];
    uint4 o;
    o.x = f2tf(f.x); o.y = f2tf(f.y); o.z = f2tf(f.z); o.w = f2tf(f.w);
    *(uint4*)&dst[i] = o;
}

// ---------------- tf32 tensor GEMM (operands pre-converted) ------------------
__device__ __forceinline__ void gemm_tf32(
    const uint32_t* __restrict__ A, const uint32_t* __restrict__ W,
    const float* __restrict__ bias, void* __restrict__ outp,
    int mode, uint32_t* As, uint32_t* Bs)
{
    const int t    = threadIdx.x;
    const int lane = t & 31;
    const int w    = t >> 5;
    const int g    = lane >> 2;
    const int t4   = lane & 3;
    const int bm   = blockIdx.y * 128;
    const int bn   = blockIdx.x * 128;
    const int wm   = (w >> 1) * 32;
    const int wn   = (w & 1) * 64;

    const int a_m = t >> 1, a_c = (t & 1) * 8;
    const int w_k = t >> 4, w_c = (t & 15) * 8;

    const uint32_t* aptr = A + (size_t)(bm + a_m) * 1024 + a_c;
    const uint32_t* wptr = W + (size_t)w_k * 1024 + bn + w_c;

    float acc[2][8][4];
#pragma unroll
    for (int mt = 0; mt < 2; ++mt)
#pragma unroll
        for (int nt = 0; nt < 8; ++nt)
#pragma unroll
            for (int i = 0; i < 4; ++i) acc[mt][nt][i] = 0.f;

    uint4 ra0, ra1, rb0, rb1;

    ra0 = *(const uint4*)(aptr);
    ra1 = *(const uint4*)(aptr + 4);
    rb0 = *(const uint4*)(wptr);
    rb1 = *(const uint4*)(wptr + 4);
    *(uint4*)&As[a_m * ASTR + a_c]     = ra0;
    *(uint4*)&As[a_m * ASTR + a_c + 4] = ra1;
    *(uint4*)&Bs[w_k * BSTR + w_c]     = rb0;
    *(uint4*)&Bs[w_k * BSTR + w_c + 4] = rb1;
    __syncthreads();

    for (int it = 0; it < 64; ++it) {
        const int buf = it & 1;
        if (it < 63) {
            const int k0 = (it + 1) * 16;
            ra0 = *(const uint4*)(aptr + k0);
            ra1 = *(const uint4*)(aptr + k0 + 4);
            rb0 = *(const uint4*)(wptr + (size_t)k0 * 1024);
            rb1 = *(const uint4*)(wptr + (size_t)k0 * 1024 + 4);
        }
        const uint32_t* Ab = As + buf * (128 * ASTR);
        const uint32_t* Bb = Bs + buf * (16 * BSTR);
#pragma unroll
        for (int ks = 0; ks < 2; ++ks) {
            uint32_t af[2][4];
#pragma unroll
            for (int mt = 0; mt < 2; ++mt) {
                const int r0 = wm + mt * 16 + g;
                af[mt][0] = Ab[r0       * ASTR + ks * 8 + t4];
                af[mt][1] = Ab[(r0 + 8) * ASTR + ks * 8 + t4];
                af[mt][2] = Ab[r0       * ASTR + ks * 8 + t4 + 4];
                af[mt][3] = Ab[(r0 + 8) * ASTR + ks * 8 + t4 + 4];
            }
#pragma unroll
            for (int nt = 0; nt < 8; ++nt) {
                const int nc = wn + nt * 8 + g;
                uint32_t b0 = Bb[(ks * 8 + t4)     * BSTR + nc];
                uint32_t b1 = Bb[(ks * 8 + t4 + 4) * BSTR + nc];
                mma8(acc[0][nt], af[0], b0, b1);
                mma8(acc[1][nt], af[1], b0, b1);
            }
        }
        if (it < 63) {
            uint32_t* a_s = As + (buf ^ 1) * (128 * ASTR) + a_m * ASTR + a_c;
            *(uint4*)(a_s)     = ra0;
            *(uint4*)(a_s + 4) = ra1;
            uint32_t* b_s = Bs + (buf ^ 1) * (16 * BSTR) + w_k * BSTR + w_c;
            *(uint4*)(b_s)     = rb0;
            *(uint4*)(b_s + 4) = rb1;
        }
        __syncthreads();
    }

#pragma unroll
    for (int mt = 0; mt < 2; ++mt) {
        const int m0 = bm + wm + mt * 16 + g;
#pragma unroll
        for (int nt = 0; nt < 8; ++nt) {
            const int n0 = bn + wn + nt * 8 + 2 * t4;
            const float bz0 = bias[n0], bz1 = bias[n0 + 1];
            float v00 = acc[mt][nt][0] + bz0;
            float v01 = acc[mt][nt][1] + bz1;
            float v10 = acc[mt][nt][2] + bz0;
            float v11 = acc[mt][nt][3] + bz1;
            if (mode == 0) {
                float* out = (float*)outp;
                *(float2*)&out[(size_t)m0 * 1024 + n0]       = make_float2(v00, v01);
                *(float2*)&out[(size_t)(m0 + 8) * 1024 + n0] = make_float2(v10, v11);
            } else {
                uint32_t* out = (uint32_t*)outp;
                const int b0i = m0 >> 11, s0 = m0 & 2047;
                const int h = n0 >> 6, d = n0 & 63;
                const int bh = b0i * NHEAD + h;
                if (mode == 1) {
                    *(uint2*)&out[((size_t)bh * SEQ + s0) * DK + d] =
                        make_uint2(f2tf(v00 * 0.125f), f2tf(v01 * 0.125f));
                    *(uint2*)&out[((size_t)bh * SEQ + s0 + 8) * DK + d] =
                        make_uint2(f2tf(v10 * 0.125f), f2tf(v11 * 0.125f));
                } else if (mode == 3) {
                    *(uint2*)&out[((size_t)bh * SEQ + s0) * DK + d] =
                        make_uint2(f2tf(v00), f2tf(v01));
                    *(uint2*)&out[((size_t)bh * SEQ + s0 + 8) * DK + d] =
                        make_uint2(f2tf(v10), f2tf(v11));
                } else {
                    uint32_t* ob = out + (size_t)bh * DK * SEQ;
                    ob[(size_t)d       * SEQ + s0]     = f2tf(v00);
                    ob[(size_t)(d + 1) * SEQ + s0]     = f2tf(v01);
                    ob[(size_t)d       * SEQ + s0 + 8] = f2tf(v10);
                    ob[(size_t)(d + 1) * SEQ + s0 + 8] = f2tf(v11);
                }
            }
        }
    }
}

__global__ void __launch_bounds__(256) qkv_gemm_p(
    const float* __restrict__ bq, const float* __restrict__ bk,
    const float* __restrict__ bv)
{
    __shared__ uint32_t As[2 * 128 * ASTR];
    __shared__ uint32_t Bs[2 * 16 * BSTR];
    const int z = blockIdx.z;
    const uint32_t* A    = (z == 0) ? g_qin : (z == 1) ? g_kin : g_vin;
    const uint32_t* W    = (z == 0) ? g_wqc : (z == 1) ? g_wkc : g_wvc;
    const float*    bias = (z == 0) ? bq    : (z == 1) ? bk    : bv;
    uint32_t* out        = (z == 0) ? g_qh  : (z == 1) ? g_kT  : g_vh;
    gemm_tf32(A, W, bias, out, z + 1, As, Bs);
}

__global__ void __launch_bounds__(256) out_gemm(
    const float* __restrict__ bo, float* __restrict__ out)
{
    __shared__ uint32_t As[2 * 128 * ASTR];
    __shared__ uint32_t Bs[2 * 16 * BSTR];
    gemm_tf32(g_ctx, g_woc, bo, out, 0, As, Bs);
}

// ---------------- attention: flash-style 2-pass -------------------------------
// CTA: 64 q rows x 2048 keys. 512 threads = 16 warps.
__global__ void __launch_bounds__(512) attn_k(float* __restrict__ attn_out)
{
    extern __shared__ uint32_t smu[];
    uint32_t* qs = smu;                         // 64*QSTR
    uint32_t* ks = qs + 64 * QSTR;              // 64*KSTR
    uint32_t* vs = ks + 64 * KSTR;              // 2 * 128*VSTR (also pass1 K buf1)
    uint32_t* ps = vs + 2 * 128 * VSTR;         // 64*PSTR
    float* fmm = (float*)(ps + 64 * PSTR);      // 64
    float* fls = fmm + 64;                      // 64
    float* sm_m = (float*)ps;                   // 16*64 (pass1 scratch)
    float* sm_l = sm_m + 1024;

    const int t    = threadIdx.x;
    const int lane = t & 31;
    const int w    = t >> 5;       // 0..15
    const int g    = lane >> 2;
    const int t4   = lane & 3;
    const int bh   = blockIdx.y;
    const int q0   = blockIdx.x * QROWS;
    const int jb   = w * 8;        // scores: key segment (8 keys)
    const int mh   = w >> 3;       // PV: m-half
    const int ncol = (w & 7) * 8;  // PV: d columns

    const uint32_t qs_b = (uint32_t)__cvta_generic_to_shared(qs);
    const uint32_t ps_b = (uint32_t)__cvta_generic_to_shared(ps);
    const uint32_t qlane = ((lane & 15) * QSTR + (lane >> 4) * 4) * 4;
    const uint32_t plane = ((lane & 15) * PSTR + (lane >> 4) * 4) * 4;

    // load Q tile (tf32, pre-scaled)
    {
        const uint32_t* qb = g_qh + ((size_t)bh * SEQ + q0) * DK;
        const int r = t >> 3, c4 = (t & 7) * 8;
        *(uint4*)&qs[r * QSTR + c4]     = *(const uint4*)&qb[r * DK + c4];
        *(uint4*)&qs[r * QSTR + c4 + 4] = *(const uint4*)&qb[r * DK + c4 + 4];
    }

    const uint32_t* kT  = g_kT + (size_t)bh * DK * SEQ;
    const uint32_t* vbg = g_vh + (size_t)bh * SEQ * DK;

    int kd[4], kj[4], vk[4], vd[4];
#pragma unroll
    for (int r = 0; r < 4; ++r) {
        int lin = r * 512 + t;
        kd[r] = lin >> 5;  kj[r] = (lin & 31) * 4;
        vk[r] = lin >> 4;  vd[r] = (lin & 15) * 4;
    }

    // ============== pass 1: row stats ==============
    float mrow[8], lrow[8];
#pragma unroll
    for (int i = 0; i < 8; ++i) { mrow[i] = -1e30f; lrow[i] = 0.f; }

#pragma unroll
    for (int r = 0; r < 4; ++r)
        *(uint4*)&ks[kd[r] * KSTR + kj[r]] =
            *(const uint4*)&kT[(size_t)kd[r] * SEQ + kj[r]];
    __syncthreads();

    for (int c = 0; c < NCH; ++c) {
        uint4 kreg[4];
        if (c < NCH - 1) {
#pragma unroll
            for (int r = 0; r < 4; ++r)
                kreg[r] = *(const uint4*)&kT[(size_t)kd[r] * SEQ + (c + 1) * CHUNK + kj[r]];
        }
        const uint32_t* kb_ = (c & 1) ? vs : ks;
        float sacc[4][4];
#pragma unroll
        for (int mt = 0; mt < 4; ++mt)
#pragma unroll
            for (int i = 0; i < 4; ++i) sacc[mt][i] = 0.f;
#pragma unroll
        for (int kb = 0; kb < 8; ++kb) {
            uint32_t b0 = kb_[(kb * 8 + t4)     * KSTR + jb + g];
            uint32_t b1 = kb_[(kb * 8 + t4 + 4) * KSTR + jb + g];
#pragma unroll
            for (int mt = 0; mt < 4; ++mt) {
                uint32_t a[4];
                ldsm4(a, qs_b + qlane + (mt * 16 * QSTR + kb * 8) * 4);
                mma8(sacc[mt], a, b0, b1);
            }
        }
#pragma unroll
        for (int mt = 0; mt < 4; ++mt) {
#pragma unroll
            for (int hf = 0; hf < 2; ++hf) {
                const int i = mt * 2 + hf;
                float v0 = sacc[mt][hf * 2], v1 = sacc[mt][hf * 2 + 1];
                float cm = fmaxf(v0, v1);
                cm = fmaxf(cm, __shfl_xor_sync(~0u, cm, 1));
                cm = fmaxf(cm, __shfl_xor_sync(~0u, cm, 2));
                float mn = fmaxf(mrow[i], cm);
                float cs = __expf(v0 - mn) + __expf(v1 - mn);
                cs += __shfl_xor_sync(~0u, cs, 1);
                cs += __shfl_xor_sync(~0u, cs, 2);
                lrow[i] = lrow[i] * __expf(mrow[i] - mn) + cs;
                mrow[i] = mn;
            }
        }
        if (c < NCH - 1) {
            uint32_t* dst = ((c + 1) & 1) ? vs : ks;
#pragma unroll
            for (int r = 0; r < 4; ++r)
                *(uint4*)&dst[kd[r] * KSTR + kj[r]] = kreg[r];
        }
        __syncthreads();
    }

    // cross-warp stat reduce
    if (t4 == 0) {
#pragma unroll
        for (int i = 0; i < 8; ++i) {
            const int row = (i >> 1) * 16 + g + (i & 1) * 8;
            sm_m[w * 64 + row] = mrow[i];
            sm_l[w * 64 + row] = lrow[i];
        }
    }
    __syncthreads();
    if (t < 64) {
        float fm = -1e30f;
#pragma unroll
        for (int ww = 0; ww < 16; ++ww) fm = fmaxf(fm, sm_m[ww * 64 + t]);
        float fl = 0.f;
#pragma unroll
        for (int ww = 0; ww < 16; ++ww)
            fl += sm_l[ww * 64 + t] * __expf(sm_m[ww * 64 + t] - fm);
        fmm[t] = fm;
        fls[t] = 1.0f / fl;
    }
    __syncthreads();

    float fmv[8], flv[8];
#pragma unroll
    for (int i = 0; i < 8; ++i) {
        const int row = (i >> 1) * 16 + g + (i & 1) * 8;
        fmv[i] = fmm[row];
        flv[i] = fls[row];
    }
    __syncthreads();

    // ============== pass 2: P write + P@V ==============
#pragma unroll
    for (int r = 0; r < 4; ++r) {
        *(uint4*)&ks[kd[r] * KSTR + kj[r]] =
            *(const uint4*)&kT[(size_t)kd[r] * SEQ + kj[r]];
        *(uint4*)&vs[vk[r] * VSTR + vd[r]] =
            *(const uint4*)&vbg[(size_t)vk[r] * DK + vd[r]];
    }
    __syncthreads();

    float oacc[2][4] = {{0, 0, 0, 0}, {0, 0, 0, 0}};
    float* attn_base = attn_out + ((size_t)bh * SEQ + q0) * SEQ;

    for (int c = 0; c < NCH; ++c) {
        uint4 kreg[4], vreg[4];
        if (c < NCH - 1) {
#pragma unroll
            for (int r = 0; r < 4; ++r) {
                kreg[r] = *(const uint4*)&kT[(size_t)kd[r] * SEQ + (c + 1) * CHUNK + kj[r]];
                vreg[r] = *(const uint4*)&vbg[((size_t)(c + 1) * CHUNK + vk[r]) * DK + vd[r]];
            }
        }
        // scores (K single-buffered in ks)
        float sacc[4][4];
#pragma unroll
        for (int mt = 0; mt < 4; ++mt)
#pragma unroll
            for (int i = 0; i < 4; ++i) sacc[mt][i] = 0.f;
#pragma unroll
        for (int kb = 0; kb < 8; ++kb) {
            uint32_t b0 = ks[(kb * 8 + t4)     * KSTR + jb + g];
            uint32_t b1 = ks[(kb * 8 + t4 + 4) * KSTR + jb + g];
#pragma unroll
            for (int mt = 0; mt < 4; ++mt) {
                uint32_t a[4];
                ldsm4(a, qs_b + qlane + (mt * 16 * QSTR + kb * 8) * 4);
                mma8(sacc[mt], a, b0, b1);
            }
        }
        // p = exp(s - m) * invl  -> ps (tf32 bits, rna)
#pragma unroll
        for (int mt = 0; mt < 4; ++mt) {
#pragma unroll
            for (int hf = 0; hf < 2; ++hf) {
                const int i = mt * 2 + hf;
                float p0 = __expf(sacc[mt][hf * 2]     - fmv[i]) * flv[i];
                float p1 = __expf(sacc[mt][hf * 2 + 1] - fmv[i]) * flv[i];
                *(uint2*)&ps[(mt * 16 + g + hf * 8) * PSTR + jb + 2 * t4] =
                    make_uint2(f2tf(p0), f2tf(p1));
            }
        }
        __syncthreads();   // ps ready; all warps done reading ks

        // P @ V  (warp: d cols ncol..ncol+7, m-tiles 2mh, 2mh+1)
        const uint32_t* vb_ = vs + (c & 1) * (128 * VSTR);
#pragma unroll
        for (int kb = 0; kb < 16; ++kb) {
            uint32_t b0 = vb_[(kb * 8 + t4)     * VSTR + ncol + g];
            uint32_t b1 = vb_[(kb * 8 + t4 + 4) * VSTR + ncol + g];
#pragma unroll
            for (int mi = 0; mi < 2; ++mi) {
                uint32_t a[4];
                ldsm4(a, ps_b + plane + (((mh * 2 + mi) * 16) * PSTR + kb * 8) * 4);
                mma8(oacc[mi], a, b0, b1);
            }
        }
        // coalesced attn write (streaming): 64 rows x 128 cols = 2048 float4
#pragma unroll
        for (int r = 0; r < 4; ++r) {
            const int lin = r * 512 + t;
            const int row = lin >> 5;            // 0..63
            const int c4  = (lin & 31) * 4;      // 0..124
            uint4 pv = *(uint4*)&ps[row * PSTR + c4];
            __stcs((float4*)&attn_base[(size_t)row * SEQ + c * CHUNK + c4],
                   *(float4*)&pv);
        }
        if (c < NCH - 1) {
            uint32_t* vdst = vs + ((c + 1) & 1) * (128 * VSTR);
#pragma unroll
            for (int r = 0; r < 4; ++r) {
                *(uint4*)&ks[kd[r] * KSTR + kj[r]]   = kreg[r];
                *(uint4*)&vdst[vk[r] * VSTR + vd[r]] = vreg[r];
            }
        }
        __syncthreads();
    }

    // epilogue: ctx (tf32 bits), layout [b*S+s][h*64+d]
    const int b = bh >> 4, h = bh & 15;
#pragma unroll
    for (int mi = 0; mi < 2; ++mi) {
        const int s0 = q0 + (mh * 2 + mi) * 16 + g;
        *(uint2*)&g_ctx[((size_t)b * SEQ + s0) * D_MODEL + h * DK + ncol + 2 * t4] =
            make_uint2(f2tf(oacc[mi][0]), f2tf(oacc[mi][1]));
        *(uint2*)&g_ctx[((size_t)b * SEQ + s0 + 8) * D_MODEL + h * DK + ncol + 2 * t4] =
            make_uint2(f2tf(oacc[mi][2]), f2tf(oacc[mi][3]));
    }
}

// ---------------- launch -----------------------------------------------------
extern "C" void kernel_launch(void* const* d_in, const int* in_sizes, int n_in,
                              void* d_out, int out_size)
{
    (void)in_sizes; (void)n_in; (void)out_size;
    const float* q  = (const float*)d_in[0];
    const float* k  = (const float*)d_in[1];
    const float* v  = (const float*)d_in[2];
    const float* wq = (const float*)d_in[3];
    const float* bq = (const float*)d_in[4];
    const float* wk = (const float*)d_in[5];
    const float* bk = (const float*)d_in[6];
    const float* wv = (const float*)d_in[7];
    const float* bv = (const float*)d_in[8];
    const float* wo = (const float*)d_in[9];
    const float* bo = (const float*)d_in[10];

    float* out  = (float*)d_out;                       // [B,S,D]
    float* attn = out + (size_t)MROWS * D_MODEL;       // [B,H,S,S]

    const int smem = (64 * QSTR + 64 * KSTR + 2 * 128 * VSTR + 64 * PSTR + 128) * 4;
    cudaFuncSetAttribute(attn_k, cudaFuncAttributeMaxDynamicSharedMemorySize, smem);

    cvt_inputs <<<dim3(MROWS * D_MODEL / (256 * 4), 3), 256>>>(q, k, v);
    cvt_weights<<<dim3(D_MODEL * D_MODEL / (256 * 4), 4), 256>>>(wq, wk, wv, wo);
    qkv_gemm_p<<<dim3(8, 32, 3), 256>>>(bq, bk, bv);
    attn_k<<<dim3(SEQ / QROWS, NBH), 512, smem>>>(attn);
    out_gemm<<<dim3(8, 32), 256>>>(bo, out);
}

// round 7
// speedup vs baseline: 3.5956x; 1.2796x over previous
#include <cuda_runtime.h>
#include <cstdint>

#define D_MODEL 1024
#define NHEAD   16
#define DK      64
#define BB      2
#define SEQ     2048
#define MROWS   (BB * SEQ)   // 4096
#define NBH     (BB * NHEAD) // 32

// attention tiling
#define QROWS 64
#define CHUNK 128
#define NCH   (SEQ / CHUNK)  // 16

// padded smem strides (u32 units)
#define KSTR  136            // K chunk [64 d][128 keys]
#define VSTR  72             // V chunk [128 keys][64 d]
#define QSTR  68             // Q tile [64 rows][64 d]
#define PPAD  36             // per-warp P patch [16 rows][32 keys]
#define KBUF  (64 * KSTR)    // 8704
#define VBUF  (128 * VSTR)   // 9216

// projection GEMM strides
#define ASTR  20
#define BSTR  136

// ---------------- scratch (device globals) -----------------------------------
__device__ uint32_t g_qin[MROWS * D_MODEL];
__device__ uint32_t g_kin[MROWS * D_MODEL];
__device__ uint32_t g_vin[MROWS * D_MODEL];
__device__ uint32_t g_wqc[D_MODEL * D_MODEL];
__device__ uint32_t g_wkc[D_MODEL * D_MODEL];
__device__ uint32_t g_wvc[D_MODEL * D_MODEL];
__device__ uint32_t g_woc[D_MODEL * D_MODEL];
__device__ uint32_t g_qh [NBH * SEQ * DK];   // [bh][s][d] tf32, pre-scaled 1/8
__device__ uint32_t g_kT [NBH * DK * SEQ];   // [bh][d][s] tf32
__device__ uint32_t g_vh [NBH * SEQ * DK];   // [bh][s][d] tf32
__device__ uint32_t g_ctx[MROWS * D_MODEL];  // [b*S+s][h*64+d] tf32

// ---------------- helpers ----------------------------------------------------
__device__ __forceinline__ uint32_t f2tf(float x) {
    uint32_t u;
    asm("cvt.rna.tf32.f32 %0, %1;" : "=r"(u) : "f"(x));
    return u;
}

__device__ __forceinline__ void mma8(float* d, const uint32_t* a,
                                     uint32_t b0, uint32_t b1) {
    asm volatile(
        "mma.sync.aligned.m16n8k8.row.col.f32.tf32.tf32.f32 "
        "{%0,%1,%2,%3}, {%4,%5,%6,%7}, {%8,%9}, {%0,%1,%2,%3};"
        : "+f"(d[0]), "+f"(d[1]), "+f"(d[2]), "+f"(d[3])
        : "r"(a[0]), "r"(a[1]), "r"(a[2]), "r"(a[3]), "r"(b0), "r"(b1));
}

__device__ __forceinline__ void ldsm4(uint32_t* r, uint32_t saddr) {
    asm volatile(
        "ldmatrix.sync.aligned.m8n8.x4.shared.b16 {%0,%1,%2,%3}, [%4];"
        : "=r"(r[0]), "=r"(r[1]), "=r"(r[2]), "=r"(r[3]) : "r"(saddr));
}

__device__ __forceinline__ void cpa16(uint32_t dst, const void* src) {
    asm volatile("cp.async.cg.shared.global [%0], [%1], 16;"
                 :: "r"(dst), "l"(src) : "memory");
}
#define CPA_COMMIT() asm volatile("cp.async.commit_group;" ::: "memory")
#define CPA_WAIT1()  asm volatile("cp.async.wait_group 1;" ::: "memory")
#define CPA_WAIT0()  asm volatile("cp.async.wait_group 0;" ::: "memory")

// ---------------- pre-convert fp32 -> tf32 bits -------------------------------
__global__ void __launch_bounds__(256) cvt_inputs(
    const float* __restrict__ q, const float* __restrict__ k,
    const float* __restrict__ v)
{
    const float* src = (blockIdx.y == 0) ? q : (blockIdx.y == 1) ? k : v;
    uint32_t* dst = (blockIdx.y == 0) ? g_qin : (blockIdx.y == 1) ? g_kin : g_vin;
    const int i = (blockIdx.x * 256 + threadIdx.x) * 4;
    float4 f = *(const float4*)&src[i];
    uint4 o;
    o.x = f2tf(f.x); o.y = f2tf(f.y); o.z = f2tf(f.z); o.w = f2tf(f.w);
    *(uint4*)&dst[i] = o;
}

__global__ void __launch_bounds__(256) cvt_weights(
    const float* __restrict__ wq, const float* __restrict__ wk,
    const float* __restrict__ wv, const float* __restrict__ wo)
{
    const float* src = (blockIdx.y == 0) ? wq : (blockIdx.y == 1) ? wk
                     : (blockIdx.y == 2) ? wv : wo;
    uint32_t* dst = (blockIdx.y == 0) ? g_wqc : (blockIdx.y == 1) ? g_wkc
                  : (blockIdx.y == 2) ? g_wvc : g_woc;
    const int i = (blockIdx.x * 256 + threadIdx.x) * 4;
    float4 f = *(const float4*)&src[i];
    uint4 o;
    o.x = f2tf(f.x); o.y = f2tf(f.y); o.z = f2tf(f.z); o.w = f2tf(f.w);
    *(uint4*)&dst[i] = o;
}

// ---------------- tf32 tensor GEMM (unchanged from R6) -----------------------
__device__ __forceinline__ void gemm_tf32(
    const uint32_t* __restrict__ A, const uint32_t* __restrict__ W,
    const float* __restrict__ bias, void* __restrict__ outp,
    int mode, uint32_t* As, uint32_t* Bs)
{
    const int t    = threadIdx.x;
    const int lane = t & 31;
    const int w    = t >> 5;
    const int g    = lane >> 2;
    const int t4   = lane & 3;
    const int bm   = blockIdx.y * 128;
    const int bn   = blockIdx.x * 128;
    const int wm   = (w >> 1) * 32;
    const int wn   = (w & 1) * 64;

    const int a_m = t >> 1, a_c = (t & 1) * 8;
    const int w_k = t >> 4, w_c = (t & 15) * 8;

    const uint32_t* aptr = A + (size_t)(bm + a_m) * 1024 + a_c;
    const uint32_t* wptr = W + (size_t)w_k * 1024 + bn + w_c;

    float acc[2][8][4];
#pragma unroll
    for (int mt = 0; mt < 2; ++mt)
#pragma unroll
        for (int nt = 0; nt < 8; ++nt)
#pragma unroll
            for (int i = 0; i < 4; ++i) acc[mt][nt][i] = 0.f;

    uint4 ra0, ra1, rb0, rb1;

    ra0 = *(const uint4*)(aptr);
    ra1 = *(const uint4*)(aptr + 4);
    rb0 = *(const uint4*)(wptr);
    rb1 = *(const uint4*)(wptr + 4);
    *(uint4*)&As[a_m * ASTR + a_c]     = ra0;
    *(uint4*)&As[a_m * ASTR + a_c + 4] = ra1;
    *(uint4*)&Bs[w_k * BSTR + w_c]     = rb0;
    *(uint4*)&Bs[w_k * BSTR + w_c + 4] = rb1;
    __syncthreads();

    for (int it = 0; it < 64; ++it) {
        const int buf = it & 1;
        if (it < 63) {
            const int k0 = (it + 1) * 16;
            ra0 = *(const uint4*)(aptr + k0);
            ra1 = *(const uint4*)(aptr + k0 + 4);
            rb0 = *(const uint4*)(wptr + (size_t)k0 * 1024);
            rb1 = *(const uint4*)(wptr + (size_t)k0 * 1024 + 4);
        }
        const uint32_t* Ab = As + buf * (128 * ASTR);
        const uint32_t* Bb = Bs + buf * (16 * BSTR);
#pragma unroll
        for (int ks = 0; ks < 2; ++ks) {
            uint32_t af[2][4];
#pragma unroll
            for (int mt = 0; mt < 2; ++mt) {
                const int r0 = wm + mt * 16 + g;
                af[mt][0] = Ab[r0       * ASTR + ks * 8 + t4];
                af[mt][1] = Ab[(r0 + 8) * ASTR + ks * 8 + t4];
                af[mt][2] = Ab[r0       * ASTR + ks * 8 + t4 + 4];
                af[mt][3] = Ab[(r0 + 8) * ASTR + ks * 8 + t4 + 4];
            }
#pragma unroll
            for (int nt = 0; nt < 8; ++nt) {
                const int nc = wn + nt * 8 + g;
                uint32_t b0 = Bb[(ks * 8 + t4)     * BSTR + nc];
                uint32_t b1 = Bb[(ks * 8 + t4 + 4) * BSTR + nc];
                mma8(acc[0][nt], af[0], b0, b1);
                mma8(acc[1][nt], af[1], b0, b1);
            }
        }
        if (it < 63) {
            uint32_t* a_s = As + (buf ^ 1) * (128 * ASTR) + a_m * ASTR + a_c;
            *(uint4*)(a_s)     = ra0;
            *(uint4*)(a_s + 4) = ra1;
            uint32_t* b_s = Bs + (buf ^ 1) * (16 * BSTR) + w_k * BSTR + w_c;
            *(uint4*)(b_s)     = rb0;
            *(uint4*)(b_s + 4) = rb1;
        }
        __syncthreads();
    }

#pragma unroll
    for (int mt = 0; mt < 2; ++mt) {
        const int m0 = bm + wm + mt * 16 + g;
#pragma unroll
        for (int nt = 0; nt < 8; ++nt) {
            const int n0 = bn + wn + nt * 8 + 2 * t4;
            const float bz0 = bias[n0], bz1 = bias[n0 + 1];
            float v00 = acc[mt][nt][0] + bz0;
            float v01 = acc[mt][nt][1] + bz1;
            float v10 = acc[mt][nt][2] + bz0;
            float v11 = acc[mt][nt][3] + bz1;
            if (mode == 0) {
                float* out = (float*)outp;
                *(float2*)&out[(size_t)m0 * 1024 + n0]       = make_float2(v00, v01);
                *(float2*)&out[(size_t)(m0 + 8) * 1024 + n0] = make_float2(v10, v11);
            } else {
                uint32_t* out = (uint32_t*)outp;
                const int b0i = m0 >> 11, s0 = m0 & 2047;
                const int h = n0 >> 6, d = n0 & 63;
                const int bh = b0i * NHEAD + h;
                if (mode == 1) {
                    *(uint2*)&out[((size_t)bh * SEQ + s0) * DK + d] =
                        make_uint2(f2tf(v00 * 0.125f), f2tf(v01 * 0.125f));
                    *(uint2*)&out[((size_t)bh * SEQ + s0 + 8) * DK + d] =
                        make_uint2(f2tf(v10 * 0.125f), f2tf(v11 * 0.125f));
                } else if (mode == 3) {
                    *(uint2*)&out[((size_t)bh * SEQ + s0) * DK + d] =
                        make_uint2(f2tf(v00), f2tf(v01));
                    *(uint2*)&out[((size_t)bh * SEQ + s0 + 8) * DK + d] =
                        make_uint2(f2tf(v10), f2tf(v11));
                } else {
                    uint32_t* ob = out + (size_t)bh * DK * SEQ;
                    ob[(size_t)d       * SEQ + s0]     = f2tf(v00);
                    ob[(size_t)(d + 1) * SEQ + s0]     = f2tf(v01);
                    ob[(size_t)d       * SEQ + s0 + 8] = f2tf(v10);
                    ob[(size_t)(d + 1) * SEQ + s0 + 8] = f2tf(v11);
                }
            }
        }
    }
}

__global__ void __launch_bounds__(256) qkv_gemm_p(
    const float* __restrict__ bq, const float* __restrict__ bk,
    const float* __restrict__ bv)
{
    __shared__ uint32_t As[2 * 128 * ASTR];
    __shared__ uint32_t Bs[2 * 16 * BSTR];
    const int z = blockIdx.z;
    const uint32_t* A    = (z == 0) ? g_qin : (z == 1) ? g_kin : g_vin;
    const uint32_t* W    = (z == 0) ? g_wqc : (z == 1) ? g_wkc : g_wvc;
    const float*    bias = (z == 0) ? bq    : (z == 1) ? bk    : bv;
    uint32_t* out        = (z == 0) ? g_qh  : (z == 1) ? g_kT  : g_vh;
    gemm_tf32(A, W, bias, out, z + 1, As, Bs);
}

__global__ void __launch_bounds__(256) out_gemm(
    const float* __restrict__ bo, float* __restrict__ out)
{
    __shared__ uint32_t As[2 * 128 * ASTR];
    __shared__ uint32_t Bs[2 * 16 * BSTR];
    gemm_tf32(g_ctx, g_woc, bo, out, 0, As, Bs);
}

// ---------------- attention: flash 2-pass, register-resident fragments --------
// 512 thr = 16 warps. warp = (mg = w>>2: 16 rows, kg = w&3: 32 keys/chunk).
// Q A-frags persistent in regs; P consumed from per-warp smem patch; O in regs.
__global__ void __launch_bounds__(512) attn_k(float* __restrict__ attn_out)
{
    extern __shared__ uint32_t smu[];
    uint32_t* qs = smu;                    // 64*QSTR           = 4352
    uint32_t* ks = qs + 64 * QSTR;         // 2*KBUF            = 17408
    uint32_t* vs = ks + 2 * KBUF;          // 2*VBUF            = 18432
    uint32_t* pp = vs + 2 * VBUF;          // 16*16*PPAD        = 9216
    float* stm = (float*)(pp + 16 * 16 * PPAD);   // 256
    float* stl = stm + 256;                       // 256
    float* fmm = stl + 256;                       // 64
    float* fls = fmm + 64;                        // 64

    const int t    = threadIdx.x;
    const int lane = t & 31;
    const int w    = t >> 5;       // 0..15
    const int g    = lane >> 2;
    const int t4   = lane & 3;
    const int mg   = w >> 2;       // m-group: rows mg*16..+15
    const int kg   = w & 3;        // key-group: keys kg*32..+31 within chunk
    const int bh   = blockIdx.y;
    const int q0   = blockIdx.x * QROWS;

    const uint32_t smem_b = (uint32_t)__cvta_generic_to_shared(smu);
    const uint32_t qs_b = smem_b;
    const uint32_t ks_b = smem_b + 64 * QSTR * 4;
    const uint32_t vs_b = ks_b + 2 * KBUF * 4;
    const uint32_t pp_b = vs_b + 2 * VBUF * 4;

    const uint32_t* kT  = g_kT + (size_t)bh * DK * SEQ;
    const uint32_t* vbg = g_vh + (size_t)bh * SEQ * DK;

    int kd[4], kj[4], vk[4], vd[4];
#pragma unroll
    for (int r = 0; r < 4; ++r) {
        int lin = r * 512 + t;
        kd[r] = lin >> 5;  kj[r] = (lin & 31) * 4;
        vk[r] = lin >> 4;  vd[r] = (lin & 15) * 4;
    }

    // stage Q
    {
        const uint32_t* qb = g_qh + ((size_t)bh * SEQ + q0) * DK;
        const int r = t >> 3, c4 = (t & 7) * 8;
        *(uint4*)&qs[r * QSTR + c4]     = *(const uint4*)&qb[r * DK + c4];
        *(uint4*)&qs[r * QSTR + c4 + 4] = *(const uint4*)&qb[r * DK + c4 + 4];
    }
    // prologue: K chunk 0 -> buf 0
#pragma unroll
    for (int r = 0; r < 4; ++r)
        cpa16(ks_b + (kd[r] * KSTR + kj[r]) * 4, kT + (size_t)kd[r] * SEQ + kj[r]);
    CPA_COMMIT();
    __syncthreads();   // qs visible

    // persistent Q A-fragments (rows mg*16..+15, all 8 k-blocks)
    uint32_t afr[8][4];
    {
        const uint32_t qlane = qs_b +
            ((mg * 16 + (lane & 15)) * QSTR + (lane >> 4) * 4) * 4;
#pragma unroll
        for (int kb = 0; kb < 8; ++kb) ldsm4(afr[kb], qlane + kb * 8 * 4);
    }

    // ============== pass 1: row stats ==============
    float mrow[2] = {-1e30f, -1e30f}, lrow[2] = {0.f, 0.f};

    for (int c = 0; c < NCH; ++c) {
        __syncthreads();   // all warps done with buf (c+1)&1 from iter c-1
        if (c < NCH - 1) {
#pragma unroll
            for (int r = 0; r < 4; ++r)
                cpa16(ks_b + (((c + 1) & 1) * KBUF + kd[r] * KSTR + kj[r]) * 4,
                      kT + (size_t)kd[r] * SEQ + (c + 1) * CHUNK + kj[r]);
            CPA_COMMIT();
            CPA_WAIT1();
        } else {
            CPA_WAIT0();
        }
        __syncthreads();   // chunk c visible to all

        const uint32_t* kb_ = ks + (c & 1) * KBUF;
        float sacc[4][4];
#pragma unroll
        for (int nb = 0; nb < 4; ++nb)
#pragma unroll
            for (int i = 0; i < 4; ++i) sacc[nb][i] = 0.f;
#pragma unroll
        for (int kb = 0; kb < 8; ++kb) {
#pragma unroll
            for (int nb = 0; nb < 4; ++nb) {
                const int jc = kg * 32 + nb * 8 + g;
                uint32_t b0 = kb_[(kb * 8 + t4)     * KSTR + jc];
                uint32_t b1 = kb_[(kb * 8 + t4 + 4) * KSTR + jc];
                mma8(sacc[nb], afr[kb], b0, b1);
            }
        }
        // online stats over this warp's 32 keys
#pragma unroll
        for (int sl = 0; sl < 2; ++sl) {
            float vm = -1e30f;
#pragma unroll
            for (int nb = 0; nb < 4; ++nb)
                vm = fmaxf(vm, fmaxf(sacc[nb][sl * 2], sacc[nb][sl * 2 + 1]));
            vm = fmaxf(vm, __shfl_xor_sync(~0u, vm, 1));
            vm = fmaxf(vm, __shfl_xor_sync(~0u, vm, 2));
            const float mn = fmaxf(mrow[sl], vm);
            float cs = 0.f;
#pragma unroll
            for (int nb = 0; nb < 4; ++nb)
                cs += __expf(sacc[nb][sl * 2] - mn) + __expf(sacc[nb][sl * 2 + 1] - mn);
            cs += __shfl_xor_sync(~0u, cs, 1);
            cs += __shfl_xor_sync(~0u, cs, 2);
            lrow[sl] = lrow[sl] * __expf(mrow[sl] - mn) + cs;
            mrow[sl] = mn;
        }
    }

    // cross-key-group reduce
    if (t4 == 0) {
        stm[kg * 64 + mg * 16 + g]     = mrow[0];
        stm[kg * 64 + mg * 16 + g + 8] = mrow[1];
        stl[kg * 64 + mg * 16 + g]     = lrow[0];
        stl[kg * 64 + mg * 16 + g + 8] = lrow[1];
    }
    __syncthreads();
    if (t < 64) {
        float fm = -1e30f;
#pragma unroll
        for (int q = 0; q < 4; ++q) fm = fmaxf(fm, stm[q * 64 + t]);
        float fl = 0.f;
#pragma unroll
        for (int q = 0; q < 4; ++q) fl += stl[q * 64 + t] * __expf(stm[q * 64 + t] - fm);
        fmm[t] = fm;
        fls[t] = 1.0f / fl;
    }
    __syncthreads();
    const float fmv0 = fmm[mg * 16 + g],     flv0 = fls[mg * 16 + g];
    const float fmv1 = fmm[mg * 16 + g + 8], flv1 = fls[mg * 16 + g + 8];
    __syncthreads();

    // ============== pass 2: P write + P@V ==============
#pragma unroll
    for (int r = 0; r < 4; ++r) {
        cpa16(ks_b + (kd[r] * KSTR + kj[r]) * 4, kT + (size_t)kd[r] * SEQ + kj[r]);
        cpa16(vs_b + (vk[r] * VSTR + vd[r]) * 4, vbg + (size_t)vk[r] * DK + vd[r]);
    }
    CPA_COMMIT();

    float oacc[8][4];
#pragma unroll
    for (int nb = 0; nb < 8; ++nb)
#pragma unroll
        for (int i = 0; i < 4; ++i) oacc[nb][i] = 0.f;

    float* attn_base = attn_out + ((size_t)bh * SEQ + q0) * SEQ;
    uint32_t* ppw = pp + w * 16 * PPAD;
    const uint32_t pplane = pp_b + w * 16 * PPAD * 4 +
        ((lane & 15) * PPAD + (lane >> 4) * 4) * 4;

    for (int c = 0; c < NCH; ++c) {
        __syncthreads();
        if (c < NCH - 1) {
#pragma unroll
            for (int r = 0; r < 4; ++r) {
                cpa16(ks_b + (((c + 1) & 1) * KBUF + kd[r] * KSTR + kj[r]) * 4,
                      kT + (size_t)kd[r] * SEQ + (c + 1) * CHUNK + kj[r]);
                cpa16(vs_b + (((c + 1) & 1) * VBUF + vk[r] * VSTR + vd[r]) * 4,
                      vbg + ((size_t)(c + 1) * CHUNK + vk[r]) * DK + vd[r]);
            }
            CPA_COMMIT();
            CPA_WAIT1();
        } else {
            CPA_WAIT0();
        }
        __syncthreads();

        // scores
        const uint32_t* kb_ = ks + (c & 1) * KBUF;
        float sacc[4][4];
#pragma unroll
        for (int nb = 0; nb < 4; ++nb)
#pragma unroll
            for (int i = 0; i < 4; ++i) sacc[nb][i] = 0.f;
#pragma unroll
        for (int kb = 0; kb < 8; ++kb) {
#pragma unroll
            for (int nb = 0; nb < 4; ++nb) {
                const int jc = kg * 32 + nb * 8 + g;
                uint32_t b0 = kb_[(kb * 8 + t4)     * KSTR + jc];
                uint32_t b1 = kb_[(kb * 8 + t4 + 4) * KSTR + jc];
                mma8(sacc[nb], afr[kb], b0, b1);
            }
        }
        // p = exp(s - m) * invl: direct gmem write + tf32 patch for PV
#pragma unroll
        for (int nb = 0; nb < 4; ++nb) {
            const float p00 = __expf(sacc[nb][0] - fmv0) * flv0;
            const float p01 = __expf(sacc[nb][1] - fmv0) * flv0;
            const float p10 = __expf(sacc[nb][2] - fmv1) * flv1;
            const float p11 = __expf(sacc[nb][3] - fmv1) * flv1;
            const int pc = nb * 8 + 2 * t4;
            *(uint2*)&ppw[g * PPAD + pc]       = make_uint2(f2tf(p00), f2tf(p01));
            *(uint2*)&ppw[(g + 8) * PPAD + pc] = make_uint2(f2tf(p10), f2tf(p11));
            const int col = c * CHUNK + kg * 32 + pc;
            __stcs((float2*)&attn_base[(size_t)(mg * 16 + g) * SEQ + col],
                   make_float2(p00, p01));
            __stcs((float2*)&attn_base[(size_t)(mg * 16 + g + 8) * SEQ + col],
                   make_float2(p10, p11));
        }
        __syncwarp();

        // P @ V: warp's own 16x32 P block x V(32 keys, 64 d)
        const uint32_t* vb_ = vs + (c & 1) * VBUF;
#pragma unroll
        for (int kb = 0; kb < 4; ++kb) {
            uint32_t a[4];
            ldsm4(a, pplane + kb * 8 * 4);
            const int kbase = kg * 32 + kb * 8;
#pragma unroll
            for (int nb = 0; nb < 8; ++nb) {
                uint32_t b0 = vb_[(kbase + t4)     * VSTR + nb * 8 + g];
                uint32_t b1 = vb_[(kbase + t4 + 4) * VSTR + nb * 8 + g];
                mma8(oacc[nb], a, b0, b1);
            }
        }
    }

    // ---- O reduce across 4 key-group warps per m-group ----
    __syncthreads();
    float* osm = (float*)vs;   // 16 warps x [16][68]
#pragma unroll
    for (int nb = 0; nb < 8; ++nb) {
        const int oc = nb * 8 + 2 * t4;
        *(float2*)&osm[w * 1088 + g * 68 + oc]       = make_float2(oacc[nb][0], oacc[nb][1]);
        *(float2*)&osm[w * 1088 + (g + 8) * 68 + oc] = make_float2(oacc[nb][2], oacc[nb][3]);
    }
    __syncthreads();
    const int b = bh >> 4, h = bh & 15;
#pragma unroll
    for (int i = t; i < 4096; i += 512) {
        const int rr = i >> 6, d = i & 63;
        const int mg2 = rr >> 4, r16 = rr & 15;
        float s = 0.f;
#pragma unroll
        for (int q = 0; q < 4; ++q)
            s += osm[(mg2 * 4 + q) * 1088 + r16 * 68 + d];
        g_ctx[((size_t)b * SEQ + q0 + rr) * D_MODEL + h * DK + d] = f2tf(s);
    }
}

// ---------------- launch -----------------------------------------------------
extern "C" void kernel_launch(void* const* d_in, const int* in_sizes, int n_in,
                              void* d_out, int out_size)
{
    (void)in_sizes; (void)n_in; (void)out_size;
    const float* q  = (const float*)d_in[0];
    const float* k  = (const float*)d_in[1];
    const float* v  = (const float*)d_in[2];
    const float* wq = (const float*)d_in[3];
    const float* bq = (const float*)d_in[4];
    const float* wk = (const float*)d_in[5];
    const float* bk = (const float*)d_in[6];
    const float* wv = (const float*)d_in[7];
    const float* bv = (const float*)d_in[8];
    const float* wo = (const float*)d_in[9];
    const float* bo = (const float*)d_in[10];

    float* out  = (float*)d_out;                       // [B,S,D]
    float* attn = out + (size_t)MROWS * D_MODEL;       // [B,H,S,S]

    const int smem = (64 * QSTR + 2 * KBUF + 2 * VBUF + 16 * 16 * PPAD + 640) * 4;
    cudaFuncSetAttribute(attn_k, cudaFuncAttributeMaxDynamicSharedMemorySize, smem);

    cvt_inputs <<<dim3(MROWS * D_MODEL / (256 * 4), 3), 256>>>(q, k, v);
    cvt_weights<<<dim3(D_MODEL * D_MODEL / (256 * 4), 4), 256>>>(wq, wk, wv, wo);
    qkv_gemm_p<<<dim3(8, 32, 3), 256>>>(bq, bk, bv);
    attn_k<<<dim3(SEQ / QROWS, NBH), 512, smem>>>(attn);
    out_gemm<<<dim3(8, 32), 256>>>(bo, out);
}